// round 1
// baseline (speedup 1.0000x reference)
#include <cuda_runtime.h>
#include <cuda_bf16.h>
#include <cstdint>

// ---------------- scratch (__device__ globals; no allocs allowed) ----------
#define NTOK   4096          // B*N = 2*2048
#define DM     512
#define NSEQ   2048
#define NHEADS 8
#define DK     64

__device__ float g_Qf[NTOK * DM];
__device__ float g_Kf[NTOK * DM];
__device__ float g_Vf[NTOK * DM];
__device__ float g_Kpart[16 * 1024];
__device__ float g_ksum[1024];
__device__ float g_Spart[32 * 16 * DK * DK];
__device__ float g_S[16 * DK * DK];
__device__ float g_OH[NTOK * DM];

// ---------------- bf16-split GEMM: C[m,n] = sum_k A[m,k]*B[n,k] (+bias,+act)
// hi/lo bf16 decomposition on the fly; fp32 accumulate via mma.sync m16n8k16.
#define GS_BM 128
#define GS_BN 128
#define GS_BK 32
#define GS_ST 40   // BK + 8 pad (conflict-free fragment loads)

__device__ __forceinline__ void mma16816(float* c, const uint32_t* a, const uint32_t* b) {
    asm volatile(
        "mma.sync.aligned.m16n8k16.row.col.f32.bf16.bf16.f32 "
        "{%0,%1,%2,%3},{%4,%5,%6,%7},{%8,%9},{%0,%1,%2,%3};"
        : "+f"(c[0]), "+f"(c[1]), "+f"(c[2]), "+f"(c[3])
        : "r"(a[0]), "r"(a[1]), "r"(a[2]), "r"(a[3]), "r"(b[0]), "r"(b[1]));
}

__device__ __forceinline__ uint32_t lds_u32(const __nv_bfloat16* s, int r, int k) {
    return *reinterpret_cast<const uint32_t*>(&s[r * GS_ST + k]);
}

__device__ __forceinline__ void cvt_split(float x, __nv_bfloat16& hi, __nv_bfloat16& lo) {
    hi = __float2bfloat16(x);
    lo = __float2bfloat16(x - __bfloat162float(hi));
}

__global__ __launch_bounds__(256)
void gemm_split(const float* __restrict__ A, long long lda,
                const float* __restrict__ B, long long ldb,
                float* __restrict__ C, long long ldc,
                int M, int N, int K,
                const float* __restrict__ bias, int act,
                int heads,
                long long sAb, long long sAh,
                long long sBb, long long sBh,
                long long sCb, long long sCh)
{
    __shared__ __nv_bfloat16 sAhi[GS_BM * GS_ST];
    __shared__ __nv_bfloat16 sAlo[GS_BM * GS_ST];
    __shared__ __nv_bfloat16 sBhi[GS_BN * GS_ST];
    __shared__ __nv_bfloat16 sBlo[GS_BN * GS_ST];

    int z = blockIdx.z;
    int zb = z / heads, zh = z % heads;
    A += zb * sAb + zh * sAh;
    B += zb * sBb + zh * sBh;
    C += zb * sCb + zh * sCh;

    int m0 = blockIdx.y * GS_BM;
    int n0 = blockIdx.x * GS_BN;
    int t = threadIdx.x;
    int lane = t & 31, warp = t >> 5;
    int wm = (warp >> 1) * 32;   // 4 warps along M
    int wn = (warp & 1) * 64;    // 2 warps along N
    int grp = lane >> 2, tig = lane & 3;

    float acc[2][8][4];
    #pragma unroll
    for (int i = 0; i < 2; i++)
        #pragma unroll
        for (int j = 0; j < 8; j++)
            #pragma unroll
            for (int l = 0; l < 4; l++) acc[i][j][l] = 0.f;

    for (int kt = 0; kt < K; kt += GS_BK) {
        // stage A and B tiles (fp32 -> hi/lo bf16)
        #pragma unroll
        for (int j = 0; j < 4; j++) {
            int id = t + j * 256;
            int r = id >> 3, c = (id & 7) * 4;
            float4 va = *reinterpret_cast<const float4*>(A + (long long)(m0 + r) * lda + kt + c);
            float4 vb = *reinterpret_cast<const float4*>(B + (long long)(n0 + r) * ldb + kt + c);
            __nv_bfloat16 h0, h1, h2, h3, l0, l1, l2, l3;
            cvt_split(va.x, h0, l0); cvt_split(va.y, h1, l1);
            cvt_split(va.z, h2, l2); cvt_split(va.w, h3, l3);
            *reinterpret_cast<__nv_bfloat162*>(&sAhi[r * GS_ST + c])     = __nv_bfloat162(h0, h1);
            *reinterpret_cast<__nv_bfloat162*>(&sAhi[r * GS_ST + c + 2]) = __nv_bfloat162(h2, h3);
            *reinterpret_cast<__nv_bfloat162*>(&sAlo[r * GS_ST + c])     = __nv_bfloat162(l0, l1);
            *reinterpret_cast<__nv_bfloat162*>(&sAlo[r * GS_ST + c + 2]) = __nv_bfloat162(l2, l3);
            cvt_split(vb.x, h0, l0); cvt_split(vb.y, h1, l1);
            cvt_split(vb.z, h2, l2); cvt_split(vb.w, h3, l3);
            *reinterpret_cast<__nv_bfloat162*>(&sBhi[r * GS_ST + c])     = __nv_bfloat162(h0, h1);
            *reinterpret_cast<__nv_bfloat162*>(&sBhi[r * GS_ST + c + 2]) = __nv_bfloat162(h2, h3);
            *reinterpret_cast<__nv_bfloat162*>(&sBlo[r * GS_ST + c])     = __nv_bfloat162(l0, l1);
            *reinterpret_cast<__nv_bfloat162*>(&sBlo[r * GS_ST + c + 2]) = __nv_bfloat162(l2, l3);
        }
        __syncthreads();

        #pragma unroll
        for (int kk = 0; kk < GS_BK; kk += 16) {
            uint32_t ah[2][4], al[2][4], bh[8][2], bl[8][2];
            int kb = kk + tig * 2;
            #pragma unroll
            for (int mi = 0; mi < 2; mi++) {
                int r = wm + mi * 16 + grp;
                ah[mi][0] = lds_u32(sAhi, r,     kb);
                ah[mi][1] = lds_u32(sAhi, r + 8, kb);
                ah[mi][2] = lds_u32(sAhi, r,     kb + 8);
                ah[mi][3] = lds_u32(sAhi, r + 8, kb + 8);
                al[mi][0] = lds_u32(sAlo, r,     kb);
                al[mi][1] = lds_u32(sAlo, r + 8, kb);
                al[mi][2] = lds_u32(sAlo, r,     kb + 8);
                al[mi][3] = lds_u32(sAlo, r + 8, kb + 8);
            }
            #pragma unroll
            for (int ni = 0; ni < 8; ni++) {
                int r = wn + ni * 8 + grp;
                bh[ni][0] = lds_u32(sBhi, r, kb);
                bh[ni][1] = lds_u32(sBhi, r, kb + 8);
                bl[ni][0] = lds_u32(sBlo, r, kb);
                bl[ni][1] = lds_u32(sBlo, r, kb + 8);
            }
            #pragma unroll
            for (int mi = 0; mi < 2; mi++)
                #pragma unroll
                for (int ni = 0; ni < 8; ni++) {
                    mma16816(acc[mi][ni], ah[mi], bh[ni]);
                    mma16816(acc[mi][ni], ah[mi], bl[ni]);
                    mma16816(acc[mi][ni], al[mi], bh[ni]);
                }
        }
        __syncthreads();
    }

    // epilogue: bias + optional elu(x)+1, write fp32
    #pragma unroll
    for (int mi = 0; mi < 2; mi++) {
        #pragma unroll
        for (int ni = 0; ni < 8; ni++) {
            int row = m0 + wm + mi * 16 + grp;
            int col = n0 + wn + ni * 8 + tig * 2;
            float b0 = 0.f, b1 = 0.f;
            if (bias) { b0 = bias[col]; b1 = bias[col + 1]; }
            float v0 = acc[mi][ni][0] + b0;
            float v1 = acc[mi][ni][1] + b1;
            float v2 = acc[mi][ni][2] + b0;
            float v3 = acc[mi][ni][3] + b1;
            if (act) {
                v0 = (v0 > 0.f) ? v0 + 1.f : expf(v0);
                v1 = (v1 > 0.f) ? v1 + 1.f : expf(v1);
                v2 = (v2 > 0.f) ? v2 + 1.f : expf(v2);
                v3 = (v3 > 0.f) ? v3 + 1.f : expf(v3);
            }
            *reinterpret_cast<float2*>(C + (long long)row * ldc + col)       = make_float2(v0, v1);
            *reinterpret_cast<float2*>(C + (long long)(row + 8) * ldc + col) = make_float2(v2, v3);
        }
    }
}

// ---------------- normalization kernels ------------------------------------
__global__ void qnorm_kernel(float* __restrict__ Q) {
    int row = blockIdx.x, t = threadIdx.x;
    float v = Q[(long long)row * DM + t];
    float s = v;
    #pragma unroll
    for (int o = 16; o > 0; o >>= 1) s += __shfl_xor_sync(0xffffffffu, s, o);
    __shared__ float ws[16];
    if ((t & 31) == 0) ws[t >> 5] = s;
    __syncthreads();
    int h = t >> 6;
    float hs = ws[2 * h] + ws[2 * h + 1];
    Q[(long long)row * DM + t] = v / (hs + 1e-8f);
}

__global__ void ksum_part_kernel(const float* __restrict__ K, float* __restrict__ Kpart) {
    int chunk = blockIdx.x;          // 16 chunks of 128 rows
    int bd = blockIdx.y;             // 8: b(2) x dgroup(4)
    int b = bd >> 2;
    int d = (bd & 3) * 128 + threadIdx.x;
    long long base = ((long long)b * NSEQ + chunk * 128) * DM + d;
    float s = 0.f;
    #pragma unroll 8
    for (int n = 0; n < 128; n++) s += K[base + (long long)n * DM];
    Kpart[chunk * 1024 + b * DM + d] = s;
}

__global__ void ksum_reduce_kernel(const float* __restrict__ Kpart, float* __restrict__ ks) {
    int t = threadIdx.x;             // 1024
    float s = 0.f;
    #pragma unroll
    for (int c = 0; c < 16; c++) s += Kpart[c * 1024 + t];
    ks[t] = s;
}

__global__ void knorm_kernel(float* __restrict__ K, const float* __restrict__ ks) {
    int row = blockIdx.x, t = threadIdx.x;
    int b = row >> 11;
    K[(long long)row * DM + t] /= (ks[b * DM + t] + 1e-8f);
}

// ---------------- S = Kn^T V per (b,h), chunked over n ----------------------
__global__ void s_part_kernel(const float* __restrict__ Kn, const float* __restrict__ V,
                              float* __restrict__ Spart) {
    int chunk = blockIdx.x;          // 32 chunks of 64 rows
    int bh = blockIdx.y;
    int b = bh >> 3, h = bh & 7;
    int t = threadIdx.x;
    int d = t & 63, q = t >> 6;      // q in 0..3 -> e range q*16
    __shared__ float Kt[64][64];
    __shared__ float Vt[64][64];
    float acc[16];
    #pragma unroll
    for (int j = 0; j < 16; j++) acc[j] = 0.f;
    long long base = ((long long)b * NSEQ + chunk * 64) * DM + h * DK;
    #pragma unroll
    for (int j = 0; j < 16; j++) {
        int id = t + j * 256;
        int nl = id >> 6, dd = id & 63;
        Kt[nl][dd] = Kn[base + (long long)nl * DM + dd];
        Vt[nl][dd] = V[base + (long long)nl * DM + dd];
    }
    __syncthreads();
    for (int nn = 0; nn < 64; nn++) {
        float kv = Kt[nn][d];
        const float4* vr = reinterpret_cast<const float4*>(&Vt[nn][q * 16]);
        #pragma unroll
        for (int j4 = 0; j4 < 4; j4++) {
            float4 v = vr[j4];
            acc[j4 * 4 + 0] += kv * v.x;
            acc[j4 * 4 + 1] += kv * v.y;
            acc[j4 * 4 + 2] += kv * v.z;
            acc[j4 * 4 + 3] += kv * v.w;
        }
    }
    float* o = Spart + ((long long)chunk * 16 + bh) * (DK * DK) + d * DK + q * 16;
    #pragma unroll
    for (int j4 = 0; j4 < 4; j4++)
        reinterpret_cast<float4*>(o)[j4] = make_float4(acc[j4*4], acc[j4*4+1], acc[j4*4+2], acc[j4*4+3]);
}

__global__ void s_reduce_kernel(const float* __restrict__ Spart, float* __restrict__ S) {
    int i = blockIdx.x * 1024 + threadIdx.x;   // 64 blocks -> 65536
    float s = 0.f;
    #pragma unroll
    for (int c = 0; c < 32; c++) s += Spart[(long long)c * 65536 + i];
    S[i] = s;
}

// ---------------- OH = Qn @ S per (b,h) -------------------------------------
__global__ void oh_kernel(const float* __restrict__ Qn, const float* __restrict__ S,
                          float* __restrict__ OH) {
    int mc = blockIdx.x;             // 16 chunks of 128 rows
    int bh = blockIdx.y;
    int b = bh >> 3, h = bh & 7;
    int t = threadIdx.x;
    int e4 = t & 15, r = t >> 4;     // 16 rows x 16 float4-lanes
    __shared__ float Ss[64][64];
    __shared__ float Qs[16][64];
    #pragma unroll
    for (int j = 0; j < 16; j++) {
        int id = t + j * 256;
        Ss[id >> 6][id & 63] = S[(long long)bh * (DK * DK) + id];
    }
    for (int it = 0; it < 8; it++) {
        int mrow = mc * 128 + it * 16;
        __syncthreads();
        #pragma unroll
        for (int j = 0; j < 4; j++) {
            int id = t + j * 256;
            int rr = id >> 6, dd = id & 63;
            Qs[rr][dd] = Qn[((long long)b * NSEQ + mrow + rr) * DM + h * DK + dd];
        }
        __syncthreads();
        float4 a = make_float4(0.f, 0.f, 0.f, 0.f);
        #pragma unroll
        for (int dd = 0; dd < 64; dd++) {
            float qd = Qs[r][dd];
            float4 s4 = *reinterpret_cast<const float4*>(&Ss[dd][e4 * 4]);
            a.x += qd * s4.x; a.y += qd * s4.y; a.z += qd * s4.z; a.w += qd * s4.w;
        }
        *reinterpret_cast<float4*>(&OH[((long long)b * NSEQ + mrow + r) * DM + h * DK + e4 * 4]) = a;
    }
}

// ---------------- launch ----------------------------------------------------
extern "C" void kernel_launch(void* const* d_in, const int* in_sizes, int n_in,
                              void* d_out, int out_size) {
    const float* q  = (const float*)d_in[0];
    const float* k  = (const float*)d_in[1];
    const float* v  = (const float*)d_in[2];
    const float* Wq = (const float*)d_in[3];
    const float* bq = (const float*)d_in[4];
    const float* Wk = (const float*)d_in[5];
    const float* bk = (const float*)d_in[6];
    const float* Wv = (const float*)d_in[7];
    const float* bv = (const float*)d_in[8];
    const float* Wo = (const float*)d_in[9];
    const float* bo = (const float*)d_in[10];

    float* out = (float*)d_out;                       // [2,2048,512]
    float* att = out + (long long)NTOK * DM;          // [2,8,2048,2048]

    float *Qf, *Kf, *Vf, *Kpart, *ks, *Spart, *S, *OH;
    cudaGetSymbolAddress((void**)&Qf, g_Qf);
    cudaGetSymbolAddress((void**)&Kf, g_Kf);
    cudaGetSymbolAddress((void**)&Vf, g_Vf);
    cudaGetSymbolAddress((void**)&Kpart, g_Kpart);
    cudaGetSymbolAddress((void**)&ks, g_ksum);
    cudaGetSymbolAddress((void**)&Spart, g_Spart);
    cudaGetSymbolAddress((void**)&S, g_S);
    cudaGetSymbolAddress((void**)&OH, g_OH);

    dim3 gproj(DM / GS_BN, NTOK / GS_BM, 1);          // (4, 32)

    // 1-3: projections (+ elu+1 for Q,K)
    gemm_split<<<gproj, 256>>>(q, DM, Wq, DM, Qf, DM, NTOK, DM, DM, bq, 1, 1, 0, 0, 0, 0, 0, 0);
    gemm_split<<<gproj, 256>>>(k, DM, Wk, DM, Kf, DM, NTOK, DM, DM, bk, 1, 1, 0, 0, 0, 0, 0, 0);
    gemm_split<<<gproj, 256>>>(v, DM, Wv, DM, Vf, DM, NTOK, DM, DM, bv, 0, 1, 0, 0, 0, 0, 0, 0);

    // 4: Qn (row-normalize per head, in-place)
    qnorm_kernel<<<NTOK, DM>>>(Qf);

    // 5-7: Kn (column-normalize over sequence, in-place)
    ksum_part_kernel<<<dim3(16, 8), 128>>>(Kf, Kpart);
    ksum_reduce_kernel<<<1, 1024>>>(Kpart, ks);
    knorm_kernel<<<NTOK, DM>>>(Kf, ks);

    // 8: attention_weights = Qn @ Kn^T per (b,h) -> d_out att region
    gemm_split<<<dim3(NSEQ / GS_BN, NSEQ / GS_BM, 16), 256>>>(
        Qf, DM, Kf, DM, att, NSEQ,
        NSEQ, NSEQ, DK, nullptr, 0,
        NHEADS,
        (long long)NSEQ * DM, (long long)DK,
        (long long)NSEQ * DM, (long long)DK,
        (long long)NHEADS * NSEQ * NSEQ, (long long)NSEQ * NSEQ);

    // 9-11: out_heads = Qn @ (Kn^T V)
    s_part_kernel<<<dim3(32, 16), 256>>>(Kf, Vf, Spart);
    s_reduce_kernel<<<64, 1024>>>(Spart, S);
    oh_kernel<<<dim3(16, 16), 256>>>(Qf, S, OH);

    // 12: final projection -> d_out
    gemm_split<<<gproj, 256>>>(OH, DM, Wo, DM, out, DM, NTOK, DM, DM, bo, 0, 1, 0, 0, 0, 0, 0, 0);
}

// round 2
// speedup vs baseline: 1.2216x; 1.2216x over previous
#include <cuda_runtime.h>
#include <cuda_bf16.h>
#include <cstdint>

#define NTOK   4096          // B*N = 2*2048
#define DM     512
#define NSEQ   2048
#define NHEADS 8
#define DK     64

// ---------------- scratch (__device__ globals; no allocs allowed) ----------
__device__ float g_Qf[NTOK * DM];
__device__ float g_Kf[NTOK * DM];
__device__ float g_Vf[NTOK * DM];
__device__ __nv_bfloat16 g_qh[NTOK * DM], g_ql[NTOK * DM];
__device__ __nv_bfloat16 g_kh[NTOK * DM], g_kl[NTOK * DM];
__device__ __nv_bfloat16 g_vh[NTOK * DM], g_vl[NTOK * DM];
__device__ __nv_bfloat16 g_Wqh[DM * DM], g_Wql[DM * DM];
__device__ __nv_bfloat16 g_Wkh[DM * DM], g_Wkl[DM * DM];
__device__ __nv_bfloat16 g_Wvh[DM * DM], g_Wvl[DM * DM];
__device__ __nv_bfloat16 g_Woh[DM * DM], g_Wol[DM * DM];
__device__ __nv_bfloat16 g_Qnh[NTOK * DM], g_Qnl[NTOK * DM];
__device__ __nv_bfloat16 g_Knh[NTOK * DM], g_Knl[NTOK * DM];
__device__ __nv_bfloat16 g_OHh[NTOK * DM], g_OHl[NTOK * DM];
__device__ float g_Kpart[16 * 1024];
__device__ float g_ksum[1024];
__device__ float g_Spart[32 * 16 * DK * DK];
__device__ float g_S[16 * DK * DK];

// ---------------- helpers ---------------------------------------------------
__device__ __forceinline__ void cvt_split(float x, __nv_bfloat16& hi, __nv_bfloat16& lo) {
    hi = __float2bfloat16(x);
    lo = __float2bfloat16(x - __bfloat162float(hi));
}

__device__ __forceinline__ uint32_t pack2(__nv_bfloat16 a, __nv_bfloat16 b) {
    __nv_bfloat162 t(a, b);
    return *reinterpret_cast<uint32_t*>(&t);
}

__device__ __forceinline__ void mma16816(float* c, const uint32_t* a, const uint32_t* b) {
    asm volatile(
        "mma.sync.aligned.m16n8k16.row.col.f32.bf16.bf16.f32 "
        "{%0,%1,%2,%3},{%4,%5,%6,%7},{%8,%9},{%0,%1,%2,%3};"
        : "+f"(c[0]), "+f"(c[1]), "+f"(c[2]), "+f"(c[3])
        : "r"(a[0]), "r"(a[1]), "r"(a[2]), "r"(a[3]), "r"(b[0]), "r"(b[1]));
}

__device__ __forceinline__ uint32_t s_u32(const __nv_bfloat16* p) {
    return *reinterpret_cast<const uint32_t*>(p);
}

// ---------------- fp32 -> bf16 hi/lo conversion kernels ---------------------
__global__ void cvt3_kernel(const float* __restrict__ x0, const float* __restrict__ x1,
                            const float* __restrict__ x2,
                            __nv_bfloat16* __restrict__ h0, __nv_bfloat16* __restrict__ l0,
                            __nv_bfloat16* __restrict__ h1, __nv_bfloat16* __restrict__ l1,
                            __nv_bfloat16* __restrict__ h2, __nv_bfloat16* __restrict__ l2)
{
    int i = blockIdx.x * blockDim.x + threadIdx.x;
    const float* x = x0; __nv_bfloat16* h = h0; __nv_bfloat16* l = l0;
    if (blockIdx.y == 1) { x = x1; h = h1; l = l1; }
    else if (blockIdx.y == 2) { x = x2; h = h2; l = l2; }
    float4 v = reinterpret_cast<const float4*>(x)[i];
    __nv_bfloat16 a, b, c, d, e, f, g, hh;
    cvt_split(v.x, a, e); cvt_split(v.y, b, f);
    cvt_split(v.z, c, g); cvt_split(v.w, d, hh);
    uint2 ph; ph.x = pack2(a, b); ph.y = pack2(c, d);
    uint2 pl; pl.x = pack2(e, f); pl.y = pack2(g, hh);
    reinterpret_cast<uint2*>(h)[i] = ph;
    reinterpret_cast<uint2*>(l)[i] = pl;
}

__global__ void cvt4_kernel(const float* __restrict__ x0, const float* __restrict__ x1,
                            const float* __restrict__ x2, const float* __restrict__ x3,
                            __nv_bfloat16* __restrict__ h0, __nv_bfloat16* __restrict__ l0,
                            __nv_bfloat16* __restrict__ h1, __nv_bfloat16* __restrict__ l1,
                            __nv_bfloat16* __restrict__ h2, __nv_bfloat16* __restrict__ l2,
                            __nv_bfloat16* __restrict__ h3, __nv_bfloat16* __restrict__ l3)
{
    int i = blockIdx.x * blockDim.x + threadIdx.x;
    const float* x = x0; __nv_bfloat16* h = h0; __nv_bfloat16* l = l0;
    if (blockIdx.y == 1) { x = x1; h = h1; l = l1; }
    else if (blockIdx.y == 2) { x = x2; h = h2; l = l2; }
    else if (blockIdx.y == 3) { x = x3; h = h3; l = l3; }
    float4 v = reinterpret_cast<const float4*>(x)[i];
    __nv_bfloat16 a, b, c, d, e, f, g, hh;
    cvt_split(v.x, a, e); cvt_split(v.y, b, f);
    cvt_split(v.z, c, g); cvt_split(v.w, d, hh);
    uint2 ph; ph.x = pack2(a, b); ph.y = pack2(c, d);
    uint2 pl; pl.x = pack2(e, f); pl.y = pack2(g, hh);
    reinterpret_cast<uint2*>(h)[i] = ph;
    reinterpret_cast<uint2*>(l)[i] = pl;
}

// ---------------- pipelined bf16 hi/lo GEMM ---------------------------------
// C[m,n] = sum_k A[m,k]*B[n,k] with 3-term hi/lo expansion, fp32 accumulate.
// BM=128, BN=BNT (64 or 128), BK=32, 2-stage cp.async double buffer.
#define GST 40   // BK + 8 pad

template<int BNT>
__global__ __launch_bounds__(256)
void gemm_bf16(const __nv_bfloat16* __restrict__ Ahi, const __nv_bfloat16* __restrict__ Alo,
               long long lda,
               const __nv_bfloat16* __restrict__ Bhi, const __nv_bfloat16* __restrict__ Blo,
               long long ldb,
               float* __restrict__ C, long long ldc, int K,
               const float* __restrict__ bias, int act, int streamC, int heads,
               long long sAb, long long sAh, long long sBb, long long sBh,
               long long sCb, long long sCh)
{
    extern __shared__ __nv_bfloat16 sm[];
    constexpr int ASZ = 128 * GST;
    constexpr int BSZ = BNT * GST;
    constexpr int STAGE = 2 * ASZ + 2 * BSZ;    // elems per stage
    constexpr int NI = BNT / 16;                 // per-warp n fragments

    int z = blockIdx.z, zb = z / heads, zh = z - zb * heads;
    long long aoff = zb * sAb + zh * sAh;
    long long boff = zb * sBb + zh * sBh;
    Ahi += aoff; Alo += aoff; Bhi += boff; Blo += boff;
    C += zb * sCb + zh * sCh;

    int m0 = blockIdx.y * 128, n0 = blockIdx.x * BNT;
    int t = threadIdx.x, lane = t & 31, warp = t >> 5;
    int wm = (warp >> 1) * 32, wn = (warp & 1) * (BNT / 2);
    int grp = lane >> 4 ? 0 : 0, tig = lane & 3;   // placeholder, fixed below
    grp = lane >> 2;
    uint32_t sb = (uint32_t)__cvta_generic_to_shared(sm);

    float acc[2][NI][4];
    #pragma unroll
    for (int i = 0; i < 2; i++)
        #pragma unroll
        for (int j = 0; j < NI; j++)
            #pragma unroll
            for (int l = 0; l < 4; l++) acc[i][j][l] = 0.f;

    auto issue = [&](int s, int kt) {
        constexpr int NCH = 4 + BNT / 32;      // 16B chunks per thread
        #pragma unroll
        for (int j = 0; j < NCH; j++) {
            int c = t + j * 256;
            const __nv_bfloat16* src;
            int off;
            if (c < 512) {
                int r = c >> 2, co = (c & 3) << 3;
                src = Ahi + (long long)(m0 + r) * lda + kt + co;
                off = r * GST + co;
            } else if (c < 1024) {
                int w = c - 512, r = w >> 2, co = (w & 3) << 3;
                src = Alo + (long long)(m0 + r) * lda + kt + co;
                off = ASZ + r * GST + co;
            } else if (c < 1024 + BNT * 4) {
                int w = c - 1024, r = w >> 2, co = (w & 3) << 3;
                src = Bhi + (long long)(n0 + r) * ldb + kt + co;
                off = 2 * ASZ + r * GST + co;
            } else {
                int w = c - 1024 - BNT * 4, r = w >> 2, co = (w & 3) << 3;
                src = Blo + (long long)(n0 + r) * ldb + kt + co;
                off = 2 * ASZ + BSZ + r * GST + co;
            }
            uint32_t d = sb + (uint32_t)(s * STAGE + off) * 2u;
            asm volatile("cp.async.cg.shared.global [%0],[%1],16;\n" :: "r"(d), "l"(src));
        }
        asm volatile("cp.async.commit_group;\n" ::);
    };

    int nt = K >> 5;
    issue(0, 0);
    for (int i = 0; i < nt; i++) {
        int cur = i & 1;
        if (i + 1 < nt) {
            issue(cur ^ 1, (i + 1) << 5);
            asm volatile("cp.async.wait_group 1;\n" ::);
        } else {
            asm volatile("cp.async.wait_group 0;\n" ::);
        }
        __syncthreads();
        const __nv_bfloat16* pAh = sm + cur * STAGE;
        const __nv_bfloat16* pAl = pAh + ASZ;
        const __nv_bfloat16* pBh = pAl + ASZ;
        const __nv_bfloat16* pBl = pBh + BSZ;

        #pragma unroll
        for (int kk = 0; kk < 32; kk += 16) {
            int kb = kk + tig * 2;
            uint32_t ah[2][4], al[2][4], bh[NI][2], bl[NI][2];
            #pragma unroll
            for (int mi = 0; mi < 2; mi++) {
                int r = wm + mi * 16 + grp;
                ah[mi][0] = s_u32(pAh + r * GST + kb);
                ah[mi][1] = s_u32(pAh + (r + 8) * GST + kb);
                ah[mi][2] = s_u32(pAh + r * GST + kb + 8);
                ah[mi][3] = s_u32(pAh + (r + 8) * GST + kb + 8);
                al[mi][0] = s_u32(pAl + r * GST + kb);
                al[mi][1] = s_u32(pAl + (r + 8) * GST + kb);
                al[mi][2] = s_u32(pAl + r * GST + kb + 8);
                al[mi][3] = s_u32(pAl + (r + 8) * GST + kb + 8);
            }
            #pragma unroll
            for (int ni = 0; ni < NI; ni++) {
                int r = wn + ni * 8 + grp;
                bh[ni][0] = s_u32(pBh + r * GST + kb);
                bh[ni][1] = s_u32(pBh + r * GST + kb + 8);
                bl[ni][0] = s_u32(pBl + r * GST + kb);
                bl[ni][1] = s_u32(pBl + r * GST + kb + 8);
            }
            #pragma unroll
            for (int mi = 0; mi < 2; mi++)
                #pragma unroll
                for (int ni = 0; ni < NI; ni++) {
                    mma16816(acc[mi][ni], ah[mi], bh[ni]);
                    mma16816(acc[mi][ni], ah[mi], bl[ni]);
                    mma16816(acc[mi][ni], al[mi], bh[ni]);
                }
        }
        __syncthreads();
    }

    // epilogue: bias + optional elu(x)+1, fp32 out (optionally streaming)
    #pragma unroll
    for (int mi = 0; mi < 2; mi++) {
        #pragma unroll
        for (int ni = 0; ni < NI; ni++) {
            int row = m0 + wm + mi * 16 + grp;
            int col = n0 + wn + ni * 8 + tig * 2;
            float b0 = 0.f, b1 = 0.f;
            if (bias) { b0 = bias[col]; b1 = bias[col + 1]; }
            float v0 = acc[mi][ni][0] + b0;
            float v1 = acc[mi][ni][1] + b1;
            float v2 = acc[mi][ni][2] + b0;
            float v3 = acc[mi][ni][3] + b1;
            if (act) {
                v0 = (v0 > 0.f) ? v0 + 1.f : expf(v0);
                v1 = (v1 > 0.f) ? v1 + 1.f : expf(v1);
                v2 = (v2 > 0.f) ? v2 + 1.f : expf(v2);
                v3 = (v3 > 0.f) ? v3 + 1.f : expf(v3);
            }
            float2* a0 = reinterpret_cast<float2*>(C + (long long)row * ldc + col);
            float2* a1 = reinterpret_cast<float2*>(C + (long long)(row + 8) * ldc + col);
            float2 p0 = make_float2(v0, v1);
            float2 p1 = make_float2(v2, v3);
            if (streamC) { __stcs(a0, p0); __stcs(a1, p1); }
            else { *a0 = p0; *a1 = p1; }
        }
    }
}

// ---------------- normalization kernels (fused hi/lo output) ----------------
__global__ void qnorm_kernel(float* __restrict__ Q,
                             __nv_bfloat16* __restrict__ Qh, __nv_bfloat16* __restrict__ Ql) {
    int row = blockIdx.x, t = threadIdx.x;
    long long idx = (long long)row * DM + t;
    float v = Q[idx];
    float s = v;
    #pragma unroll
    for (int o = 16; o > 0; o >>= 1) s += __shfl_xor_sync(0xffffffffu, s, o);
    __shared__ float ws[16];
    if ((t & 31) == 0) ws[t >> 5] = s;
    __syncthreads();
    int h = t >> 6;
    float hs = ws[2 * h] + ws[2 * h + 1];
    float r = v / (hs + 1e-8f);
    Q[idx] = r;
    __nv_bfloat16 hi, lo;
    cvt_split(r, hi, lo);
    Qh[idx] = hi; Ql[idx] = lo;
}

__global__ void ksum_part_kernel(const float* __restrict__ K, float* __restrict__ Kpart) {
    int chunk = blockIdx.x;          // 16 chunks of 128 rows
    int bd = blockIdx.y;             // 8: b(2) x dgroup(4)
    int b = bd >> 2;
    int d = (bd & 3) * 128 + threadIdx.x;
    long long base = ((long long)b * NSEQ + chunk * 128) * DM + d;
    float s = 0.f;
    #pragma unroll 8
    for (int n = 0; n < 128; n++) s += K[base + (long long)n * DM];
    Kpart[chunk * 1024 + b * DM + d] = s;
}

__global__ void ksum_reduce_kernel(const float* __restrict__ Kpart, float* __restrict__ ks) {
    int t = threadIdx.x;             // 1024
    float s = 0.f;
    #pragma unroll
    for (int c = 0; c < 16; c++) s += Kpart[c * 1024 + t];
    ks[t] = s;
}

__global__ void knorm_kernel(float* __restrict__ K, const float* __restrict__ ks,
                             __nv_bfloat16* __restrict__ Kh, __nv_bfloat16* __restrict__ Kl) {
    int row = blockIdx.x, t = threadIdx.x;
    int b = row >> 11;
    long long idx = (long long)row * DM + t;
    float r = K[idx] / (ks[b * DM + t] + 1e-8f);
    K[idx] = r;
    __nv_bfloat16 hi, lo;
    cvt_split(r, hi, lo);
    Kh[idx] = hi; Kl[idx] = lo;
}

// ---------------- S = Kn^T V per (b,h), chunked over n ----------------------
__global__ void s_part_kernel(const float* __restrict__ Kn, const float* __restrict__ V,
                              float* __restrict__ Spart) {
    int chunk = blockIdx.x;          // 32 chunks of 64 rows
    int bh = blockIdx.y;
    int b = bh >> 3, h = bh & 7;
    int t = threadIdx.x;
    int d = t & 63, q = t >> 6;
    __shared__ float Kt[64][64];
    __shared__ float Vt[64][64];
    float acc[16];
    #pragma unroll
    for (int j = 0; j < 16; j++) acc[j] = 0.f;
    long long base = ((long long)b * NSEQ + chunk * 64) * DM + h * DK;
    #pragma unroll
    for (int j = 0; j < 16; j++) {
        int id = t + j * 256;
        int nl = id >> 6, dd = id & 63;
        Kt[nl][dd] = Kn[base + (long long)nl * DM + dd];
        Vt[nl][dd] = V[base + (long long)nl * DM + dd];
    }
    __syncthreads();
    for (int nn = 0; nn < 64; nn++) {
        float kv = Kt[nn][d];
        const float4* vr = reinterpret_cast<const float4*>(&Vt[nn][q * 16]);
        #pragma unroll
        for (int j4 = 0; j4 < 4; j4++) {
            float4 v = vr[j4];
            acc[j4 * 4 + 0] += kv * v.x;
            acc[j4 * 4 + 1] += kv * v.y;
            acc[j4 * 4 + 2] += kv * v.z;
            acc[j4 * 4 + 3] += kv * v.w;
        }
    }
    float* o = Spart + ((long long)chunk * 16 + bh) * (DK * DK) + d * DK + q * 16;
    #pragma unroll
    for (int j4 = 0; j4 < 4; j4++)
        reinterpret_cast<float4*>(o)[j4] =
            make_float4(acc[j4 * 4], acc[j4 * 4 + 1], acc[j4 * 4 + 2], acc[j4 * 4 + 3]);
}

__global__ void s_reduce_kernel(const float* __restrict__ Spart, float* __restrict__ S) {
    int i = blockIdx.x * 1024 + threadIdx.x;   // 64 blocks -> 65536
    float s = 0.f;
    #pragma unroll
    for (int c = 0; c < 32; c++) s += Spart[(long long)c * 65536 + i];
    S[i] = s;
}

// ---------------- OH = Qn @ S per (b,h); writes bf16 hi/lo ------------------
__global__ void oh_kernel(const float* __restrict__ Qn, const float* __restrict__ S,
                          __nv_bfloat16* __restrict__ OHh, __nv_bfloat16* __restrict__ OHl) {
    int mc = blockIdx.x;             // 16 chunks of 128 rows
    int bh = blockIdx.y;
    int b = bh >> 3, h = bh & 7;
    int t = threadIdx.x;
    int e4 = t & 15, r = t >> 4;
    __shared__ float Ss[64][64];
    __shared__ float Qs[16][64];
    #pragma unroll
    for (int j = 0; j < 16; j++) {
        int id = t + j * 256;
        Ss[id >> 6][id & 63] = S[(long long)bh * (DK * DK) + id];
    }
    for (int it = 0; it < 8; it++) {
        int mrow = mc * 128 + it * 16;
        __syncthreads();
        #pragma unroll
        for (int j = 0; j < 4; j++) {
            int id = t + j * 256;
            int rr = id >> 6, dd = id & 63;
            Qs[rr][dd] = Qn[((long long)b * NSEQ + mrow + rr) * DM + h * DK + dd];
        }
        __syncthreads();
        float4 a = make_float4(0.f, 0.f, 0.f, 0.f);
        #pragma unroll
        for (int dd = 0; dd < 64; dd++) {
            float qd = Qs[r][dd];
            float4 s4 = *reinterpret_cast<const float4*>(&Ss[dd][e4 * 4]);
            a.x += qd * s4.x; a.y += qd * s4.y; a.z += qd * s4.z; a.w += qd * s4.w;
        }
        __nv_bfloat16 h0, h1, h2, h3, l0, l1, l2, l3;
        cvt_split(a.x, h0, l0); cvt_split(a.y, h1, l1);
        cvt_split(a.z, h2, l2); cvt_split(a.w, h3, l3);
        long long oidx = ((long long)b * NSEQ + mrow + r) * DM + h * DK + e4 * 4;
        uint2 ph; ph.x = pack2(h0, h1); ph.y = pack2(h2, h3);
        uint2 pl; pl.x = pack2(l0, l1); pl.y = pack2(l2, l3);
        *reinterpret_cast<uint2*>(OHh + oidx) = ph;
        *reinterpret_cast<uint2*>(OHl + oidx) = pl;
    }
}

// ---------------- launch ----------------------------------------------------
extern "C" void kernel_launch(void* const* d_in, const int* in_sizes, int n_in,
                              void* d_out, int out_size) {
    const float* q  = (const float*)d_in[0];
    const float* k  = (const float*)d_in[1];
    const float* v  = (const float*)d_in[2];
    const float* Wq = (const float*)d_in[3];
    const float* bq = (const float*)d_in[4];
    const float* Wk = (const float*)d_in[5];
    const float* bk = (const float*)d_in[6];
    const float* Wv = (const float*)d_in[7];
    const float* bv = (const float*)d_in[8];
    const float* Wo = (const float*)d_in[9];
    const float* bo = (const float*)d_in[10];

    float* out = (float*)d_out;                       // [2,2048,512]
    float* att = out + (long long)NTOK * DM;          // [2,8,2048,2048]

    float *Qf, *Kf, *Vf, *Kpart, *ks, *Spart, *S;
    __nv_bfloat16 *qh, *ql, *kh, *kl, *vh, *vl;
    __nv_bfloat16 *Wqh, *Wql, *Wkh, *Wkl, *Wvh, *Wvl, *Woh, *Wol;
    __nv_bfloat16 *Qnh, *Qnl, *Knh, *Knl, *OHh, *OHl;
    cudaGetSymbolAddress((void**)&Qf, g_Qf);
    cudaGetSymbolAddress((void**)&Kf, g_Kf);
    cudaGetSymbolAddress((void**)&Vf, g_Vf);
    cudaGetSymbolAddress((void**)&Kpart, g_Kpart);
    cudaGetSymbolAddress((void**)&ks, g_ksum);
    cudaGetSymbolAddress((void**)&Spart, g_Spart);
    cudaGetSymbolAddress((void**)&S, g_S);
    cudaGetSymbolAddress((void**)&qh, g_qh);  cudaGetSymbolAddress((void**)&ql, g_ql);
    cudaGetSymbolAddress((void**)&kh, g_kh);  cudaGetSymbolAddress((void**)&kl, g_kl);
    cudaGetSymbolAddress((void**)&vh, g_vh);  cudaGetSymbolAddress((void**)&vl, g_vl);
    cudaGetSymbolAddress((void**)&Wqh, g_Wqh); cudaGetSymbolAddress((void**)&Wql, g_Wql);
    cudaGetSymbolAddress((void**)&Wkh, g_Wkh); cudaGetSymbolAddress((void**)&Wkl, g_Wkl);
    cudaGetSymbolAddress((void**)&Wvh, g_Wvh); cudaGetSymbolAddress((void**)&Wvl, g_Wvl);
    cudaGetSymbolAddress((void**)&Woh, g_Woh); cudaGetSymbolAddress((void**)&Wol, g_Wol);
    cudaGetSymbolAddress((void**)&Qnh, g_Qnh); cudaGetSymbolAddress((void**)&Qnl, g_Qnl);
    cudaGetSymbolAddress((void**)&Knh, g_Knh); cudaGetSymbolAddress((void**)&Knl, g_Knl);
    cudaGetSymbolAddress((void**)&OHh, g_OHh); cudaGetSymbolAddress((void**)&OHl, g_OHl);

    // dynamic smem caps (idempotent; capture-safe, not a stream op)
    cudaFuncSetAttribute(gemm_bf16<64>,  cudaFuncAttributeMaxDynamicSharedMemorySize, 61440);
    cudaFuncSetAttribute(gemm_bf16<128>, cudaFuncAttributeMaxDynamicSharedMemorySize, 81920);

    // 0: one-time fp32 -> bf16 hi/lo conversions (inputs + weights)
    cvt3_kernel<<<dim3(2048, 3), 256>>>(q, k, v, qh, ql, kh, kl, vh, vl);
    cvt4_kernel<<<dim3(256, 4), 256>>>(Wq, Wk, Wv, Wo,
                                       Wqh, Wql, Wkh, Wkl, Wvh, Wvl, Woh, Wol);

    dim3 gproj(DM / 64, NTOK / 128, 1);   // (8, 32)

    // 1-3: projections (+ elu+1 fused for Q,K)
    gemm_bf16<64><<<gproj, 256, 61440>>>(qh, ql, DM, Wqh, Wql, DM, Qf, DM, DM,
                                         bq, 1, 0, 1, 0, 0, 0, 0, 0, 0);
    gemm_bf16<64><<<gproj, 256, 61440>>>(kh, kl, DM, Wkh, Wkl, DM, Kf, DM, DM,
                                         bk, 1, 0, 1, 0, 0, 0, 0, 0, 0);
    gemm_bf16<64><<<gproj, 256, 61440>>>(vh, vl, DM, Wvh, Wvl, DM, Vf, DM, DM,
                                         bv, 0, 0, 1, 0, 0, 0, 0, 0, 0);

    // 4: Qn (row-normalize per head) -> fp32 + bf16 hi/lo
    qnorm_kernel<<<NTOK, DM>>>(Qf, Qnh, Qnl);

    // 5-7: Kn (column-normalize over sequence) -> fp32 + bf16 hi/lo
    ksum_part_kernel<<<dim3(16, 8), 128>>>(Kf, Kpart);
    ksum_reduce_kernel<<<1, 1024>>>(Kpart, ks);
    knorm_kernel<<<NTOK, DM>>>(Kf, ks, Knh, Knl);

    // 8: attention_weights = Qn @ Kn^T per (b,h) -> d_out att region (streamed)
    gemm_bf16<128><<<dim3(NSEQ / 128, NSEQ / 128, 16), 256, 81920>>>(
        Qnh, Qnl, DM, Knh, Knl, DM, att, NSEQ, DK,
        nullptr, 0, 1, NHEADS,
        (long long)NSEQ * DM, (long long)DK,
        (long long)NSEQ * DM, (long long)DK,
        (long long)NHEADS * NSEQ * NSEQ, (long long)NSEQ * NSEQ);

    // 9-11: out_heads = Qn @ (Kn^T V) -> bf16 hi/lo
    s_part_kernel<<<dim3(32, 16), 256>>>(Kf, Vf, Spart);
    s_reduce_kernel<<<64, 1024>>>(Spart, S);
    oh_kernel<<<dim3(16, 16), 256>>>(Qf, S, OHh, OHl);

    // 12: final projection -> d_out (streamed)
    gemm_bf16<64><<<gproj, 256, 61440>>>(OHh, OHl, DM, Woh, Wol, DM, out, DM, DM,
                                         bo, 0, 1, 1, 0, 0, 0, 0, 0, 0);
}

// round 5
// speedup vs baseline: 1.4351x; 1.1747x over previous
#include <cuda_runtime.h>
#include <cuda_bf16.h>
#include <cstdint>

#define NTOK   4096          // B*N = 2*2048
#define DM     512
#define NSEQ   2048
#define NHEADS 8
#define DK     64

// ---------------- scratch (__device__ globals; no allocs allowed) ----------
__device__ float g_F[3 * NTOK * DM];                       // Qf,Kf,Vf fp32
__device__ __nv_bfloat16 g_XH[3 * NTOK * DM], g_XL[3 * NTOK * DM];   // q,k,v hi/lo
__device__ __nv_bfloat16 g_WH[4 * DM * DM],  g_WL[4 * DM * DM];      // Wq,Wk,Wv,Wo
__device__ __nv_bfloat16 g_Qnh[NTOK * DM], g_Qnl[NTOK * DM];
__device__ __nv_bfloat16 g_Knh[NTOK * DM], g_Knl[NTOK * DM];
__device__ __nv_bfloat16 g_OHh[NTOK * DM], g_OHl[NTOK * DM];
__device__ float g_Kpart[16 * 1024];
__device__ float g_ksum[1024];
__device__ float g_Spart[32 * 16 * DK * DK];
__device__ float g_S[16 * DK * DK];

// ---------------- helpers ---------------------------------------------------
__device__ __forceinline__ void cvt_split(float x, __nv_bfloat16& hi, __nv_bfloat16& lo) {
    hi = __float2bfloat16(x);
    lo = __float2bfloat16(x - __bfloat162float(hi));
}
__device__ __forceinline__ uint32_t pack2(__nv_bfloat16 a, __nv_bfloat16 b) {
    __nv_bfloat162 t(a, b);
    return *reinterpret_cast<uint32_t*>(&t);
}
__device__ __forceinline__ uint32_t smem_u32(const void* p) {
    uint32_t a;
    asm("{ .reg .u64 t; cvta.to.shared.u64 t, %1; cvt.u32.u64 %0, t; }" : "=r"(a) : "l"(p));
    return a;
}
__device__ __forceinline__ void mma16816(float* c, const uint32_t* a, const uint32_t* b) {
    asm volatile(
        "mma.sync.aligned.m16n8k16.row.col.f32.bf16.bf16.f32 "
        "{%0,%1,%2,%3},{%4,%5,%6,%7},{%8,%9},{%0,%1,%2,%3};"
        : "+f"(c[0]), "+f"(c[1]), "+f"(c[2]), "+f"(c[3])
        : "r"(a[0]), "r"(a[1]), "r"(a[2]), "r"(a[3]), "r"(b[0]), "r"(b[1]));
}
__device__ __forceinline__ void ldsm4(uint32_t* r, uint32_t a) {
    asm volatile("ldmatrix.sync.aligned.m8n8.x4.shared.b16 {%0,%1,%2,%3},[%4];"
                 : "=r"(r[0]), "=r"(r[1]), "=r"(r[2]), "=r"(r[3]) : "r"(a));
}

// ---------------- fp32 -> bf16 hi/lo conversion kernels ---------------------
__global__ void cvt3_kernel(const float* __restrict__ x0, const float* __restrict__ x1,
                            const float* __restrict__ x2,
                            __nv_bfloat16* __restrict__ H, __nv_bfloat16* __restrict__ L)
{
    int i = blockIdx.x * blockDim.x + threadIdx.x;
    const float* x = (blockIdx.y == 0) ? x0 : (blockIdx.y == 1) ? x1 : x2;
    long long off = (long long)blockIdx.y * (NTOK * DM / 4);
    float4 v = reinterpret_cast<const float4*>(x)[i];
    __nv_bfloat16 a, b, c, d, e, f, g, hh;
    cvt_split(v.x, a, e); cvt_split(v.y, b, f);
    cvt_split(v.z, c, g); cvt_split(v.w, d, hh);
    uint2 ph; ph.x = pack2(a, b); ph.y = pack2(c, d);
    uint2 pl; pl.x = pack2(e, f); pl.y = pack2(g, hh);
    reinterpret_cast<uint2*>(H)[off + i] = ph;
    reinterpret_cast<uint2*>(L)[off + i] = pl;
}

__global__ void cvt4_kernel(const float* __restrict__ x0, const float* __restrict__ x1,
                            const float* __restrict__ x2, const float* __restrict__ x3,
                            __nv_bfloat16* __restrict__ H, __nv_bfloat16* __restrict__ L)
{
    int i = blockIdx.x * blockDim.x + threadIdx.x;
    const float* x = x0;
    if (blockIdx.y == 1) x = x1; else if (blockIdx.y == 2) x = x2; else if (blockIdx.y == 3) x = x3;
    long long off = (long long)blockIdx.y * (DM * DM / 4);
    float4 v = reinterpret_cast<const float4*>(x)[i];
    __nv_bfloat16 a, b, c, d, e, f, g, hh;
    cvt_split(v.x, a, e); cvt_split(v.y, b, f);
    cvt_split(v.z, c, g); cvt_split(v.w, d, hh);
    uint2 ph; ph.x = pack2(a, b); ph.y = pack2(c, d);
    uint2 pl; pl.x = pack2(e, f); pl.y = pack2(g, hh);
    reinterpret_cast<uint2*>(H)[off + i] = ph;
    reinterpret_cast<uint2*>(L)[off + i] = pl;
}

// ---------------- ldmatrix-fed bf16 hi/lo GEMM ------------------------------
// C[m,n] = sum_k A[m,k]*B[n,k]; 3-term hi/lo expansion; BM=BN=128, BK=32,
// 2-stage cp.async double buffer; fragments via ldmatrix.x4.
#define GST   40                  // padded row: 32 elems + 8 (80B; LDSM conflict-free)
#define TILEB (128 * GST * 2)     // 10240 B per tile
#define STAGEB (4 * TILEB)        // Ahi,Alo,Bhi,Blo = 40960 B
#define SMTOT (2 * STAGEB)        // 81920 B

__global__ __launch_bounds__(256, 2)
void mm_kernel(const __nv_bfloat16* __restrict__ Ahi, const __nv_bfloat16* __restrict__ Alo,
               long long lda,
               const __nv_bfloat16* __restrict__ Bhi, const __nv_bfloat16* __restrict__ Blo,
               long long ldb,
               float* __restrict__ C, long long ldc, int K,
               const float* __restrict__ b0, const float* __restrict__ b1,
               const float* __restrict__ b2,
               int actmask, int streamC, int heads,
               long long sAb, long long sAh, long long sBb, long long sBh,
               long long sCb, long long sCh)
{
    extern __shared__ __nv_bfloat16 smem[];
    int z = blockIdx.z, zb = z / heads, zh = z - zb * heads;
    Ahi += zb * sAb + zh * sAh;  Alo += zb * sAb + zh * sAh;
    Bhi += zb * sBb + zh * sBh;  Blo += zb * sBb + zh * sBh;
    C   += zb * sCb + zh * sCh;
    const float* bias = (zb == 0) ? b0 : (zb == 1) ? b1 : b2;
    int act = (actmask >> zb) & 1;

    int m0 = blockIdx.y * 128, n0 = blockIdx.x * 128;
    int tid = threadIdx.x, lane = tid & 31, warp = tid >> 5;
    int wm = (warp >> 1) * 32;          // 4 warps along M
    int wn = (warp & 1) * 64;           // 2 warps along N
    int grp = lane >> 2, tig = lane & 3;
    uint32_t sb = smem_u32(smem);

    // LDSM lane address components (element units)
    int aoff = (wm + (lane & 15)) * GST + ((lane >> 4) << 3);
    int boff = (wn + ((lane >> 4) << 3) + (lane & 7)) * GST + (((lane >> 3) & 1) << 3);

    float acc[2][8][4];
    #pragma unroll
    for (int i = 0; i < 2; i++)
        #pragma unroll
        for (int j = 0; j < 8; j++)
            #pragma unroll
            for (int l = 0; l < 4; l++) acc[i][j][l] = 0.f;

    auto issue = [&](int s, int kt) {
        #pragma unroll
        for (int j = 0; j < 8; j++) {
            int id = tid + j * 256;
            int tile = id >> 9;
            int w = id & 511;
            int r = w >> 2, ce = (w & 3) * 8;
            const __nv_bfloat16* src;
            if (tile == 0)      src = Ahi + (long long)(m0 + r) * lda + kt + ce;
            else if (tile == 1) src = Alo + (long long)(m0 + r) * lda + kt + ce;
            else if (tile == 2) src = Bhi + (long long)(n0 + r) * ldb + kt + ce;
            else                src = Blo + (long long)(n0 + r) * ldb + kt + ce;
            uint32_t d = sb + (uint32_t)(s * STAGEB + tile * TILEB) + (uint32_t)(r * GST + ce) * 2u;
            asm volatile("cp.async.cg.shared.global [%0],[%1],16;\n" :: "r"(d), "l"(src));
        }
        asm volatile("cp.async.commit_group;\n" ::);
    };

    int nt = K >> 5;
    issue(0, 0);
    for (int i = 0; i < nt; i++) {
        int cur = i & 1;
        if (i + 1 < nt) {
            issue(cur ^ 1, (i + 1) << 5);
            asm volatile("cp.async.wait_group 1;\n" ::);
        } else {
            asm volatile("cp.async.wait_group 0;\n" ::);
        }
        __syncthreads();
        uint32_t sA  = sb + cur * STAGEB;
        uint32_t sAl = sA + TILEB;
        uint32_t sB  = sA + 2 * TILEB;
        uint32_t sBl = sA + 3 * TILEB;

        #pragma unroll
        for (int kk = 0; kk < 32; kk += 16) {
            uint32_t ah[2][4], al[2][4], bf[4][4];
            // A-hi + B-hi
            #pragma unroll
            for (int mi = 0; mi < 2; mi++)
                ldsm4(ah[mi], sA + (uint32_t)(aoff + mi * 16 * GST + kk) * 2u);
            #pragma unroll
            for (int n2 = 0; n2 < 4; n2++)
                ldsm4(bf[n2], sB + (uint32_t)(boff + n2 * 16 * GST + kk) * 2u);
            #pragma unroll
            for (int mi = 0; mi < 2; mi++)
                #pragma unroll
                for (int n2 = 0; n2 < 4; n2++) {
                    mma16816(acc[mi][2 * n2],     ah[mi], bf[n2]);
                    mma16816(acc[mi][2 * n2 + 1], ah[mi], bf[n2] + 2);
                }
            // A-lo x B-hi (B-hi still live)
            #pragma unroll
            for (int mi = 0; mi < 2; mi++)
                ldsm4(al[mi], sAl + (uint32_t)(aoff + mi * 16 * GST + kk) * 2u);
            #pragma unroll
            for (int mi = 0; mi < 2; mi++)
                #pragma unroll
                for (int n2 = 0; n2 < 4; n2++) {
                    mma16816(acc[mi][2 * n2],     al[mi], bf[n2]);
                    mma16816(acc[mi][2 * n2 + 1], al[mi], bf[n2] + 2);
                }
            // A-hi x B-lo (overwrite B regs)
            #pragma unroll
            for (int n2 = 0; n2 < 4; n2++)
                ldsm4(bf[n2], sBl + (uint32_t)(boff + n2 * 16 * GST + kk) * 2u);
            #pragma unroll
            for (int mi = 0; mi < 2; mi++)
                #pragma unroll
                for (int n2 = 0; n2 < 4; n2++) {
                    mma16816(acc[mi][2 * n2],     ah[mi], bf[n2]);
                    mma16816(acc[mi][2 * n2 + 1], ah[mi], bf[n2] + 2);
                }
        }
        __syncthreads();
    }

    // epilogue: bias + optional elu(x)+1, fp32 out (optionally streaming)
    #pragma unroll
    for (int mi = 0; mi < 2; mi++) {
        #pragma unroll
        for (int ni = 0; ni < 8; ni++) {
            int row = m0 + wm + mi * 16 + grp;
            int col = n0 + wn + ni * 8 + tig * 2;
            float bb0 = 0.f, bb1 = 0.f;
            if (bias) { bb0 = __ldg(&bias[col]); bb1 = __ldg(&bias[col + 1]); }
            float v0 = acc[mi][ni][0] + bb0;
            float v1 = acc[mi][ni][1] + bb1;
            float v2 = acc[mi][ni][2] + bb0;
            float v3 = acc[mi][ni][3] + bb1;
            if (act) {
                v0 = (v0 > 0.f) ? v0 + 1.f : expf(v0);
                v1 = (v1 > 0.f) ? v1 + 1.f : expf(v1);
                v2 = (v2 > 0.f) ? v2 + 1.f : expf(v2);
                v3 = (v3 > 0.f) ? v3 + 1.f : expf(v3);
            }
            float2* a0 = reinterpret_cast<float2*>(C + (long long)row * ldc + col);
            float2* a1 = reinterpret_cast<float2*>(C + (long long)(row + 8) * ldc + col);
            float2 p0 = make_float2(v0, v1);
            float2 p1 = make_float2(v2, v3);
            if (streamC) { __stcs(a0, p0); __stcs(a1, p1); }
            else { *a0 = p0; *a1 = p1; }
        }
    }
}

// ---------------- normalization kernels (fused hi/lo output) ----------------
__global__ void qnorm_kernel(float* __restrict__ Q,
                             __nv_bfloat16* __restrict__ Qh, __nv_bfloat16* __restrict__ Ql) {
    int row = blockIdx.x, t = threadIdx.x;
    long long idx = (long long)row * DM + t;
    float v = Q[idx];
    float s = v;
    #pragma unroll
    for (int o = 16; o > 0; o >>= 1) s += __shfl_xor_sync(0xffffffffu, s, o);
    __shared__ float ws[16];
    if ((t & 31) == 0) ws[t >> 5] = s;
    __syncthreads();
    int h = t >> 6;
    float hs = ws[2 * h] + ws[2 * h + 1];
    float r = v / (hs + 1e-8f);
    Q[idx] = r;
    __nv_bfloat16 hi, lo;
    cvt_split(r, hi, lo);
    Qh[idx] = hi; Ql[idx] = lo;
}

__global__ void ksum_part_kernel(const float* __restrict__ K, float* __restrict__ Kpart) {
    int chunk = blockIdx.x;
    int bd = blockIdx.y;
    int b = bd >> 2;
    int d = (bd & 3) * 128 + threadIdx.x;
    long long base = ((long long)b * NSEQ + chunk * 128) * DM + d;
    float s = 0.f;
    #pragma unroll 8
    for (int n = 0; n < 128; n++) s += K[base + (long long)n * DM];
    Kpart[chunk * 1024 + b * DM + d] = s;
}

__global__ void ksum_reduce_kernel(const float* __restrict__ Kpart, float* __restrict__ ks) {
    int t = threadIdx.x;
    float s = 0.f;
    #pragma unroll
    for (int c = 0; c < 16; c++) s += Kpart[c * 1024 + t];
    ks[t] = s;
}

__global__ void knorm_kernel(float* __restrict__ K, const float* __restrict__ ks,
                             __nv_bfloat16* __restrict__ Kh, __nv_bfloat16* __restrict__ Kl) {
    int row = blockIdx.x, t = threadIdx.x;
    int b = row >> 11;
    long long idx = (long long)row * DM + t;
    float r = K[idx] / (ks[b * DM + t] + 1e-8f);
    K[idx] = r;
    __nv_bfloat16 hi, lo;
    cvt_split(r, hi, lo);
    Kh[idx] = hi; Kl[idx] = lo;
}

// ---------------- S = Kn^T V per (b,h), chunked over n ----------------------
__global__ void s_part_kernel(const float* __restrict__ Kn, const float* __restrict__ V,
                              float* __restrict__ Spart) {
    int chunk = blockIdx.x;
    int bh = blockIdx.y;
    int b = bh >> 3, h = bh & 7;
    int t = threadIdx.x;
    int d = t & 63, q = t >> 6;
    __shared__ float Kt[64][64];
    __shared__ float Vt[64][64];
    float acc[16];
    #pragma unroll
    for (int j = 0; j < 16; j++) acc[j] = 0.f;
    long long base = ((long long)b * NSEQ + chunk * 64) * DM + h * DK;
    #pragma unroll
    for (int j = 0; j < 16; j++) {
        int id = t + j * 256;
        int nl = id >> 6, dd = id & 63;
        Kt[nl][dd] = Kn[base + (long long)nl * DM + dd];
        Vt[nl][dd] = V[base + (long long)nl * DM + dd];
    }
    __syncthreads();
    for (int nn = 0; nn < 64; nn++) {
        float kv = Kt[nn][d];
        const float4* vr = reinterpret_cast<const float4*>(&Vt[nn][q * 16]);
        #pragma unroll
        for (int j4 = 0; j4 < 4; j4++) {
            float4 v = vr[j4];
            acc[j4 * 4 + 0] += kv * v.x;
            acc[j4 * 4 + 1] += kv * v.y;
            acc[j4 * 4 + 2] += kv * v.z;
            acc[j4 * 4 + 3] += kv * v.w;
        }
    }
    float* o = Spart + ((long long)chunk * 16 + bh) * (DK * DK) + d * DK + q * 16;
    #pragma unroll
    for (int j4 = 0; j4 < 4; j4++)
        reinterpret_cast<float4*>(o)[j4] =
            make_float4(acc[j4 * 4], acc[j4 * 4 + 1], acc[j4 * 4 + 2], acc[j4 * 4 + 3]);
}

__global__ void s_reduce_kernel(const float* __restrict__ Spart, float* __restrict__ S) {
    int i = blockIdx.x * 1024 + threadIdx.x;
    float s = 0.f;
    #pragma unroll
    for (int c = 0; c < 32; c++) s += Spart[(long long)c * 65536 + i];
    S[i] = s;
}

// ---------------- OH = Qn @ S per (b,h); writes bf16 hi/lo ------------------
__global__ void oh_kernel(const float* __restrict__ Qn, const float* __restrict__ S,
                          __nv_bfloat16* __restrict__ OHh, __nv_bfloat16* __restrict__ OHl) {
    int mc = blockIdx.x;
    int bh = blockIdx.y;
    int b = bh >> 3, h = bh & 7;
    int t = threadIdx.x;
    int e4 = t & 15, r = t >> 4;
    __shared__ float Ss[64][64];
    __shared__ float Qs[16][64];
    #pragma unroll
    for (int j = 0; j < 16; j++) {
        int id = t + j * 256;
        Ss[id >> 6][id & 63] = S[(long long)bh * (DK * DK) + id];
    }
    for (int it = 0; it < 8; it++) {
        int mrow = mc * 128 + it * 16;
        __syncthreads();
        #pragma unroll
        for (int j = 0; j < 4; j++) {
            int id = t + j * 256;
            int rr = id >> 6, dd = id & 63;
            Qs[rr][dd] = Qn[((long long)b * NSEQ + mrow + rr) * DM + h * DK + dd];
        }
        __syncthreads();
        float4 a = make_float4(0.f, 0.f, 0.f, 0.f);
        #pragma unroll
        for (int dd = 0; dd < 64; dd++) {
            float qd = Qs[r][dd];
            float4 s4 = *reinterpret_cast<const float4*>(&Ss[dd][e4 * 4]);
            a.x += qd * s4.x; a.y += qd * s4.y; a.z += qd * s4.z; a.w += qd * s4.w;
        }
        __nv_bfloat16 h0, h1, h2, h3, l0, l1, l2, l3;
        cvt_split(a.x, h0, l0); cvt_split(a.y, h1, l1);
        cvt_split(a.z, h2, l2); cvt_split(a.w, h3, l3);
        long long oidx = ((long long)b * NSEQ + mrow + r) * DM + h * DK + e4 * 4;
        uint2 ph; ph.x = pack2(h0, h1); ph.y = pack2(h2, h3);
        uint2 pl; pl.x = pack2(l0, l1); pl.y = pack2(l2, l3);
        *reinterpret_cast<uint2*>(OHh + oidx) = ph;
        *reinterpret_cast<uint2*>(OHl + oidx) = pl;
    }
}

// ---------------- launch ----------------------------------------------------
extern "C" void kernel_launch(void* const* d_in, const int* in_sizes, int n_in,
                              void* d_out, int out_size) {
    const float* q  = (const float*)d_in[0];
    const float* k  = (const float*)d_in[1];
    const float* v  = (const float*)d_in[2];
    const float* Wq = (const float*)d_in[3];
    const float* bq = (const float*)d_in[4];
    const float* Wk = (const float*)d_in[5];
    const float* bk = (const float*)d_in[6];
    const float* Wv = (const float*)d_in[7];
    const float* bv = (const float*)d_in[8];
    const float* Wo = (const float*)d_in[9];
    const float* bo = (const float*)d_in[10];

    float* out = (float*)d_out;                       // [2,2048,512]
    float* att = out + (long long)NTOK * DM;          // [2,8,2048,2048]

    float *F, *Kpart, *ks, *Spart, *S;
    __nv_bfloat16 *XH, *XL, *WH, *WL, *Qnh, *Qnl, *Knh, *Knl, *OHh, *OHl;
    cudaGetSymbolAddress((void**)&F, g_F);
    cudaGetSymbolAddress((void**)&Kpart, g_Kpart);
    cudaGetSymbolAddress((void**)&ks, g_ksum);
    cudaGetSymbolAddress((void**)&Spart, g_Spart);
    cudaGetSymbolAddress((void**)&S, g_S);
    cudaGetSymbolAddress((void**)&XH, g_XH);  cudaGetSymbolAddress((void**)&XL, g_XL);
    cudaGetSymbolAddress((void**)&WH, g_WH);  cudaGetSymbolAddress((void**)&WL, g_WL);
    cudaGetSymbolAddress((void**)&Qnh, g_Qnh); cudaGetSymbolAddress((void**)&Qnl, g_Qnl);
    cudaGetSymbolAddress((void**)&Knh, g_Knh); cudaGetSymbolAddress((void**)&Knl, g_Knl);
    cudaGetSymbolAddress((void**)&OHh, g_OHh); cudaGetSymbolAddress((void**)&OHl, g_OHl);

    float* Qf = F;
    float* Kf = F + (long long)NTOK * DM;
    float* Vf = F + 2LL * NTOK * DM;

    cudaFuncSetAttribute(mm_kernel, cudaFuncAttributeMaxDynamicSharedMemorySize, SMTOT);

    // 0: one-time fp32 -> bf16 hi/lo conversions (inputs + weights)
    cvt3_kernel<<<dim3(2048, 3), 256>>>(q, k, v, XH, XL);
    cvt4_kernel<<<dim3(256, 4), 256>>>(Wq, Wk, Wv, Wo, WH, WL);

    // 1: batched projections q/k/v (+ elu+1 fused for q,k)
    mm_kernel<<<dim3(4, 32, 3), 256, SMTOT>>>(
        XH, XL, DM, WH, WL, DM, F, DM, DM,
        bq, bk, bv, 0b011, 0, 1,
        (long long)NTOK * DM, 0, (long long)DM * DM, 0, (long long)NTOK * DM, 0);

    // 2: Qn (row-normalize per head) -> fp32 + bf16 hi/lo
    qnorm_kernel<<<NTOK, DM>>>(Qf, Qnh, Qnl);

    // 3: Kn (column-normalize over sequence) -> fp32 + bf16 hi/lo
    ksum_part_kernel<<<dim3(16, 8), 128>>>(Kf, Kpart);
    ksum_reduce_kernel<<<1, 1024>>>(Kpart, ks);
    knorm_kernel<<<NTOK, DM>>>(Kf, ks, Knh, Knl);

    // 4: attention_weights = Qn @ Kn^T per (b,h) -> d_out att region (streamed)
    mm_kernel<<<dim3(16, 16, 16), 256, SMTOT>>>(
        Qnh, Qnl, DM, Knh, Knl, DM, att, NSEQ, DK,
        nullptr, nullptr, nullptr, 0, 1, NHEADS,
        (long long)NSEQ * DM, (long long)DK,
        (long long)NSEQ * DM, (long long)DK,
        (long long)NHEADS * NSEQ * NSEQ, (long long)NSEQ * NSEQ);

    // 5: out_heads = Qn @ (Kn^T V) -> bf16 hi/lo
    s_part_kernel<<<dim3(32, 16), 256>>>(Kf, Vf, Spart);
    s_reduce_kernel<<<64, 1024>>>(Spart, S);
    oh_kernel<<<dim3(16, 16), 256>>>(Qf, S, OHh, OHl);

    // 6: final projection -> d_out
    mm_kernel<<<dim3(4, 32, 1), 256, SMTOT>>>(
        OHh, OHl, DM, WH + 3LL * DM * DM, WL + 3LL * DM * DM, DM, out, DM, DM,
        bo, nullptr, nullptr, 0, 0, 1,
        0, 0, 0, 0, 0, 0);
}

// round 6
// speedup vs baseline: 1.6979x; 1.1831x over previous
#include <cuda_runtime.h>
#include <cuda_fp16.h>
#include <cstdint>

#define NTOK   4096          // B*N = 2*2048
#define DM     512
#define NSEQ   2048
#define NHEADS 8
#define DK     64

#define QSCALE 64.0f
#define KSCALE 2048.0f
#define ATT_CSCALE (1.0f / (64.0f * 2048.0f))

// ---------------- scratch (__device__ globals; no allocs allowed) ----------
__device__ float g_F[3 * NTOK * DM];                       // Qf,Kf,Vf fp32
__device__ __half g_XH[3 * NTOK * DM], g_XL[3 * NTOK * DM];   // q,k,v hi/lo
__device__ __half g_WH[4 * DM * DM],  g_WL[4 * DM * DM];      // Wq,Wk,Wv,Wo
__device__ __half g_Qnh[NTOK * DM], g_Qnl[NTOK * DM];         // Qn * 64
__device__ __half g_Knh[NTOK * DM];                           // Kn * 2048 (hi only)
__device__ __half g_OHh[NTOK * DM], g_OHl[NTOK * DM];
__device__ float g_Kpart[16 * 1024];
__device__ float g_ksum[1024];
__device__ float g_Spart[32 * 16 * DK * DK];
__device__ float g_S[16 * DK * DK];

// ---------------- helpers ---------------------------------------------------
__device__ __forceinline__ void cvt_split(float x, __half& hi, __half& lo) {
    hi = __float2half_rn(x);
    lo = __float2half_rn(x - __half2float(hi));
}
__device__ __forceinline__ uint32_t pack2(__half a, __half b) {
    __half2 t(a, b);
    return *reinterpret_cast<uint32_t*>(&t);
}
__device__ __forceinline__ uint32_t smem_u32(const void* p) {
    uint32_t a;
    asm("{ .reg .u64 t; cvta.to.shared.u64 t, %1; cvt.u32.u64 %0, t; }" : "=r"(a) : "l"(p));
    return a;
}
__device__ __forceinline__ void mma16816(float* c, const uint32_t* a, const uint32_t* b) {
    asm volatile(
        "mma.sync.aligned.m16n8k16.row.col.f32.f16.f16.f32 "
        "{%0,%1,%2,%3},{%4,%5,%6,%7},{%8,%9},{%0,%1,%2,%3};"
        : "+f"(c[0]), "+f"(c[1]), "+f"(c[2]), "+f"(c[3])
        : "r"(a[0]), "r"(a[1]), "r"(a[2]), "r"(a[3]), "r"(b[0]), "r"(b[1]));
}
__device__ __forceinline__ void ldsm4(uint32_t* r, uint32_t a) {
    asm volatile("ldmatrix.sync.aligned.m8n8.x4.shared.b16 {%0,%1,%2,%3},[%4];"
                 : "=r"(r[0]), "=r"(r[1]), "=r"(r[2]), "=r"(r[3]) : "r"(a));
}

// ---------------- fp32 -> fp16 hi/lo conversion kernels ---------------------
__global__ void cvt3_kernel(const float* __restrict__ x0, const float* __restrict__ x1,
                            const float* __restrict__ x2,
                            __half* __restrict__ H, __half* __restrict__ L)
{
    int i = blockIdx.x * blockDim.x + threadIdx.x;
    const float* x = (blockIdx.y == 0) ? x0 : (blockIdx.y == 1) ? x1 : x2;
    long long off = (long long)blockIdx.y * (NTOK * DM / 4);
    float4 v = reinterpret_cast<const float4*>(x)[i];
    __half a, b, c, d, e, f, g, hh;
    cvt_split(v.x, a, e); cvt_split(v.y, b, f);
    cvt_split(v.z, c, g); cvt_split(v.w, d, hh);
    uint2 ph; ph.x = pack2(a, b); ph.y = pack2(c, d);
    uint2 pl; pl.x = pack2(e, f); pl.y = pack2(g, hh);
    reinterpret_cast<uint2*>(H)[off + i] = ph;
    reinterpret_cast<uint2*>(L)[off + i] = pl;
}

__global__ void cvt4_kernel(const float* __restrict__ x0, const float* __restrict__ x1,
                            const float* __restrict__ x2, const float* __restrict__ x3,
                            __half* __restrict__ H, __half* __restrict__ L)
{
    int i = blockIdx.x * blockDim.x + threadIdx.x;
    const float* x = x0;
    if (blockIdx.y == 1) x = x1; else if (blockIdx.y == 2) x = x2; else if (blockIdx.y == 3) x = x3;
    long long off = (long long)blockIdx.y * (DM * DM / 4);
    float4 v = reinterpret_cast<const float4*>(x)[i];
    __half a, b, c, d, e, f, g, hh;
    cvt_split(v.x, a, e); cvt_split(v.y, b, f);
    cvt_split(v.z, c, g); cvt_split(v.w, d, hh);
    uint2 ph; ph.x = pack2(a, b); ph.y = pack2(c, d);
    uint2 pl; pl.x = pack2(e, f); pl.y = pack2(g, hh);
    reinterpret_cast<uint2*>(H)[off + i] = ph;
    reinterpret_cast<uint2*>(L)[off + i] = pl;
}

// ---------------- ldmatrix-fed fp16 hi/lo GEMM ------------------------------
// C[m,n] = cscale * sum_k A[m,k]*B[n,k]; NT-term hi/lo expansion;
// BM=BN=128, BK=32, 2-stage cp.async double buffer, ldmatrix.x4 fragments.
// NT=2: A exact (hi+lo), B hi only.  NT=3: + A-hi x B-lo.
#define GST   40                  // padded row: 32 elems + 8 (80B; LDSM conflict-free)
#define TILEB (128 * GST * 2)     // 10240 B per tile

template<int NT>
__global__ __launch_bounds__(256, 2)
void mm_kernel(const __half* __restrict__ Ahi, const __half* __restrict__ Alo,
               long long lda,
               const __half* __restrict__ Bhi, const __half* __restrict__ Blo,
               long long ldb,
               float* __restrict__ C, long long ldc, int K,
               const float* __restrict__ b0, const float* __restrict__ b1,
               const float* __restrict__ b2,
               int actmask, int streamC, float cscale, int heads,
               long long sAb, long long sAh, long long sBb, long long sBh,
               long long sCb, long long sCh)
{
    extern __shared__ __half smem[];
    constexpr int NTILE  = NT + 1;            // Ahi, Alo, Bhi[, Blo]
    constexpr int STAGEB = NTILE * TILEB;

    int z = blockIdx.z, zb = z / heads, zh = z - zb * heads;
    Ahi += zb * sAb + zh * sAh;  Alo += zb * sAb + zh * sAh;
    Bhi += zb * sBb + zh * sBh;  if (NT == 3) Blo += zb * sBb + zh * sBh;
    C   += zb * sCb + zh * sCh;
    const float* bias = (zb == 0) ? b0 : (zb == 1) ? b1 : b2;
    int act = (actmask >> zb) & 1;

    int m0 = blockIdx.y * 128, n0 = blockIdx.x * 128;
    int tid = threadIdx.x, lane = tid & 31, warp = tid >> 5;
    int wm = (warp >> 1) * 32;          // 4 warps along M
    int wn = (warp & 1) * 64;           // 2 warps along N
    int grp = lane >> 2, tig = lane & 3;
    uint32_t sb = smem_u32(smem);

    // LDSM lane address components (element units)
    int aoff = (wm + (lane & 15)) * GST + ((lane >> 4) << 3);
    int boff = (wn + ((lane >> 4) << 3) + (lane & 7)) * GST + (((lane >> 3) & 1) << 3);

    float acc[2][8][4];
    #pragma unroll
    for (int i = 0; i < 2; i++)
        #pragma unroll
        for (int j = 0; j < 8; j++)
            #pragma unroll
            for (int l = 0; l < 4; l++) acc[i][j][l] = 0.f;

    auto issue = [&](int s, int kt) {
        #pragma unroll
        for (int j = 0; j < 2 * NTILE; j++) {
            int id = tid + j * 256;
            int tile = id >> 9;
            int w = id & 511;
            int r = w >> 2, ce = (w & 3) * 8;
            const __half* src;
            if (tile == 0)      src = Ahi + (long long)(m0 + r) * lda + kt + ce;
            else if (tile == 1) src = Alo + (long long)(m0 + r) * lda + kt + ce;
            else if (tile == 2) src = Bhi + (long long)(n0 + r) * ldb + kt + ce;
            else                src = Blo + (long long)(n0 + r) * ldb + kt + ce;
            uint32_t d = sb + (uint32_t)(s * STAGEB + tile * TILEB) + (uint32_t)(r * GST + ce) * 2u;
            asm volatile("cp.async.cg.shared.global [%0],[%1],16;\n" :: "r"(d), "l"(src));
        }
        asm volatile("cp.async.commit_group;\n" ::);
    };

    int nt = K >> 5;
    issue(0, 0);
    for (int i = 0; i < nt; i++) {
        int cur = i & 1;
        if (i + 1 < nt) {
            issue(cur ^ 1, (i + 1) << 5);
            asm volatile("cp.async.wait_group 1;\n" ::);
        } else {
            asm volatile("cp.async.wait_group 0;\n" ::);
        }
        __syncthreads();
        uint32_t sA  = sb + cur * STAGEB;
        uint32_t sAl = sA + TILEB;
        uint32_t sB  = sA + 2 * TILEB;
        uint32_t sBl = sA + 3 * TILEB;

        #pragma unroll
        for (int kk = 0; kk < 32; kk += 16) {
            uint32_t ah[2][4], al[2][4], bf[4][4];
            // A-hi x B-hi
            #pragma unroll
            for (int mi = 0; mi < 2; mi++)
                ldsm4(ah[mi], sA + (uint32_t)(aoff + mi * 16 * GST + kk) * 2u);
            #pragma unroll
            for (int n2 = 0; n2 < 4; n2++)
                ldsm4(bf[n2], sB + (uint32_t)(boff + n2 * 16 * GST + kk) * 2u);
            #pragma unroll
            for (int mi = 0; mi < 2; mi++)
                #pragma unroll
                for (int n2 = 0; n2 < 4; n2++) {
                    mma16816(acc[mi][2 * n2],     ah[mi], bf[n2]);
                    mma16816(acc[mi][2 * n2 + 1], ah[mi], bf[n2] + 2);
                }
            // A-lo x B-hi (B-hi still live)
            #pragma unroll
            for (int mi = 0; mi < 2; mi++)
                ldsm4(al[mi], sAl + (uint32_t)(aoff + mi * 16 * GST + kk) * 2u);
            #pragma unroll
            for (int mi = 0; mi < 2; mi++)
                #pragma unroll
                for (int n2 = 0; n2 < 4; n2++) {
                    mma16816(acc[mi][2 * n2],     al[mi], bf[n2]);
                    mma16816(acc[mi][2 * n2 + 1], al[mi], bf[n2] + 2);
                }
            if (NT == 3) {
                // A-hi x B-lo (overwrite B regs)
                #pragma unroll
                for (int n2 = 0; n2 < 4; n2++)
                    ldsm4(bf[n2], sBl + (uint32_t)(boff + n2 * 16 * GST + kk) * 2u);
                #pragma unroll
                for (int mi = 0; mi < 2; mi++)
                    #pragma unroll
                    for (int n2 = 0; n2 < 4; n2++) {
                        mma16816(acc[mi][2 * n2],     ah[mi], bf[n2]);
                        mma16816(acc[mi][2 * n2 + 1], ah[mi], bf[n2] + 2);
                    }
            }
        }
        __syncthreads();
    }

    // epilogue: scale + bias + optional elu(x)+1, fp32 out
    #pragma unroll
    for (int mi = 0; mi < 2; mi++) {
        #pragma unroll
        for (int ni = 0; ni < 8; ni++) {
            int row = m0 + wm + mi * 16 + grp;
            int col = n0 + wn + ni * 8 + tig * 2;
            float bb0 = 0.f, bb1 = 0.f;
            if (bias) { bb0 = __ldg(&bias[col]); bb1 = __ldg(&bias[col + 1]); }
            float v0 = acc[mi][ni][0] * cscale + bb0;
            float v1 = acc[mi][ni][1] * cscale + bb1;
            float v2 = acc[mi][ni][2] * cscale + bb0;
            float v3 = acc[mi][ni][3] * cscale + bb1;
            if (act) {
                v0 = (v0 > 0.f) ? v0 + 1.f : expf(v0);
                v1 = (v1 > 0.f) ? v1 + 1.f : expf(v1);
                v2 = (v2 > 0.f) ? v2 + 1.f : expf(v2);
                v3 = (v3 > 0.f) ? v3 + 1.f : expf(v3);
            }
            float2* a0 = reinterpret_cast<float2*>(C + (long long)row * ldc + col);
            float2* a1 = reinterpret_cast<float2*>(C + (long long)(row + 8) * ldc + col);
            float2 p0 = make_float2(v0, v1);
            float2 p1 = make_float2(v2, v3);
            if (streamC) { __stcs(a0, p0); __stcs(a1, p1); }
            else { *a0 = p0; *a1 = p1; }
        }
    }
}

// ---------------- normalization kernels (fused fp16 hi/lo output) -----------
// qnorm: 256 thr = 2 rows x 128 thr (float4 each); head = 16 threads
__global__ void qnorm_kernel(float* __restrict__ Q,
                             __half* __restrict__ Qh, __half* __restrict__ Ql) {
    int t = threadIdx.x;
    int r = t >> 7, c4 = t & 127;
    long long row = blockIdx.x * 2 + r;
    long long i4 = row * 128 + c4;
    float4 v = reinterpret_cast<const float4*>(Q)[i4];
    float s = v.x + v.y + v.z + v.w;
    #pragma unroll
    for (int o = 8; o > 0; o >>= 1) s += __shfl_xor_sync(0xffffffffu, s, o);
    float inv = 1.f / (s + 1e-8f);
    float4 rr = make_float4(v.x * inv, v.y * inv, v.z * inv, v.w * inv);
    reinterpret_cast<float4*>(Q)[i4] = rr;
    __half h0, h1, h2, h3, l0, l1, l2, l3;
    cvt_split(rr.x * QSCALE, h0, l0); cvt_split(rr.y * QSCALE, h1, l1);
    cvt_split(rr.z * QSCALE, h2, l2); cvt_split(rr.w * QSCALE, h3, l3);
    uint2 ph; ph.x = pack2(h0, h1); ph.y = pack2(h2, h3);
    uint2 pl; pl.x = pack2(l0, l1); pl.y = pack2(l2, l3);
    reinterpret_cast<uint2*>(Qh)[i4] = ph;
    reinterpret_cast<uint2*>(Ql)[i4] = pl;
}

__global__ void ksum_part_kernel(const float* __restrict__ K, float* __restrict__ Kpart) {
    int chunk = blockIdx.x;
    int bd = blockIdx.y;
    int b = bd >> 2;
    int d = (bd & 3) * 128 + threadIdx.x;
    long long base = ((long long)b * NSEQ + chunk * 128) * DM + d;
    float s = 0.f;
    #pragma unroll 8
    for (int n = 0; n < 128; n++) s += K[base + (long long)n * DM];
    Kpart[chunk * 1024 + b * DM + d] = s;
}

__global__ void ksum_reduce_kernel(const float* __restrict__ Kpart, float* __restrict__ ks) {
    int t = threadIdx.x;
    float s = 0.f;
    #pragma unroll
    for (int c = 0; c < 16; c++) s += Kpart[c * 1024 + t];
    ks[t] = s;
}

// knorm: float4 per thread; writes Kf fp32 + Kn*2048 fp16 (hi only)
__global__ void knorm_kernel(float* __restrict__ K, const float* __restrict__ ks,
                             __half* __restrict__ Kh) {
    long long i4 = (long long)blockIdx.x * blockDim.x + threadIdx.x;
    long long row = i4 >> 7;
    int b = (int)(row >> 11);
    int c4 = (int)(i4 & 127);
    float4 sv = reinterpret_cast<const float4*>(ks + b * DM)[c4];
    float4 v = reinterpret_cast<const float4*>(K)[i4];
    float4 rr = make_float4(v.x / (sv.x + 1e-8f), v.y / (sv.y + 1e-8f),
                            v.z / (sv.z + 1e-8f), v.w / (sv.w + 1e-8f));
    reinterpret_cast<float4*>(K)[i4] = rr;
    uint2 ph;
    ph.x = pack2(__float2half_rn(rr.x * KSCALE), __float2half_rn(rr.y * KSCALE));
    ph.y = pack2(__float2half_rn(rr.z * KSCALE), __float2half_rn(rr.w * KSCALE));
    reinterpret_cast<uint2*>(Kh)[i4] = ph;
}

// ---------------- S = Kn^T V per (b,h), chunked over n ----------------------
__global__ void s_part_kernel(const float* __restrict__ Kn, const float* __restrict__ V,
                              float* __restrict__ Spart) {
    int chunk = blockIdx.x;
    int bh = blockIdx.y;
    int b = bh >> 3, h = bh & 7;
    int t = threadIdx.x;
    int d = t & 63, q = t >> 6;
    __shared__ float Kt[64][64];
    __shared__ float Vt[64][64];
    float acc[16];
    #pragma unroll
    for (int j = 0; j < 16; j++) acc[j] = 0.f;
    long long base = ((long long)b * NSEQ + chunk * 64) * DM + h * DK;
    #pragma unroll
    for (int j = 0; j < 16; j++) {
        int id = t + j * 256;
        int nl = id >> 6, dd = id & 63;
        Kt[nl][dd] = Kn[base + (long long)nl * DM + dd];
        Vt[nl][dd] = V[base + (long long)nl * DM + dd];
    }
    __syncthreads();
    for (int nn = 0; nn < 64; nn++) {
        float kv = Kt[nn][d];
        const float4* vr = reinterpret_cast<const float4*>(&Vt[nn][q * 16]);
        #pragma unroll
        for (int j4 = 0; j4 < 4; j4++) {
            float4 v = vr[j4];
            acc[j4 * 4 + 0] += kv * v.x;
            acc[j4 * 4 + 1] += kv * v.y;
            acc[j4 * 4 + 2] += kv * v.z;
            acc[j4 * 4 + 3] += kv * v.w;
        }
    }
    float* o = Spart + ((long long)chunk * 16 + bh) * (DK * DK) + d * DK + q * 16;
    #pragma unroll
    for (int j4 = 0; j4 < 4; j4++)
        reinterpret_cast<float4*>(o)[j4] =
            make_float4(acc[j4 * 4], acc[j4 * 4 + 1], acc[j4 * 4 + 2], acc[j4 * 4 + 3]);
}

__global__ void s_reduce_kernel(const float* __restrict__ Spart, float* __restrict__ S) {
    int i = blockIdx.x * 1024 + threadIdx.x;
    float s = 0.f;
    #pragma unroll
    for (int c = 0; c < 32; c++) s += Spart[(long long)c * 65536 + i];
    S[i] = s;
}

// ---------------- OH = Qn @ S per (b,h); writes fp16 hi/lo ------------------
__global__ void oh_kernel(const float* __restrict__ Qn, const float* __restrict__ S,
                          __half* __restrict__ OHh, __half* __restrict__ OHl) {
    int mc = blockIdx.x;
    int bh = blockIdx.y;
    int b = bh >> 3, h = bh & 7;
    int t = threadIdx.x;
    int e4 = t & 15, r = t >> 4;
    __shared__ float Ss[64][64];
    __shared__ float Qs[16][64];
    #pragma unroll
    for (int j = 0; j < 16; j++) {
        int id = t + j * 256;
        Ss[id >> 6][id & 63] = S[(long long)bh * (DK * DK) + id];
    }
    for (int it = 0; it < 8; it++) {
        int mrow = mc * 128 + it * 16;
        __syncthreads();
        #pragma unroll
        for (int j = 0; j < 4; j++) {
            int id = t + j * 256;
            int rr = id >> 6, dd = id & 63;
            Qs[rr][dd] = Qn[((long long)b * NSEQ + mrow + rr) * DM + h * DK + dd];
        }
        __syncthreads();
        float4 a = make_float4(0.f, 0.f, 0.f, 0.f);
        #pragma unroll
        for (int dd = 0; dd < 64; dd++) {
            float qd = Qs[r][dd];
            float4 s4 = *reinterpret_cast<const float4*>(&Ss[dd][e4 * 4]);
            a.x += qd * s4.x; a.y += qd * s4.y; a.z += qd * s4.z; a.w += qd * s4.w;
        }
        __half h0, h1, h2, h3, l0, l1, l2, l3;
        cvt_split(a.x, h0, l0); cvt_split(a.y, h1, l1);
        cvt_split(a.z, h2, l2); cvt_split(a.w, h3, l3);
        long long oidx = ((long long)b * NSEQ + mrow + r) * DM + h * DK + e4 * 4;
        uint2 ph; ph.x = pack2(h0, h1); ph.y = pack2(h2, h3);
        uint2 pl; pl.x = pack2(l0, l1); pl.y = pack2(l2, l3);
        *reinterpret_cast<uint2*>(OHh + oidx) = ph;
        *reinterpret_cast<uint2*>(OHl + oidx) = pl;
    }
}

// ---------------- launch ----------------------------------------------------
extern "C" void kernel_launch(void* const* d_in, const int* in_sizes, int n_in,
                              void* d_out, int out_size) {
    const float* q  = (const float*)d_in[0];
    const float* k  = (const float*)d_in[1];
    const float* v  = (const float*)d_in[2];
    const float* Wq = (const float*)d_in[3];
    const float* bq = (const float*)d_in[4];
    const float* Wk = (const float*)d_in[5];
    const float* bk = (const float*)d_in[6];
    const float* Wv = (const float*)d_in[7];
    const float* bv = (const float*)d_in[8];
    const float* Wo = (const float*)d_in[9];
    const float* bo = (const float*)d_in[10];

    float* out = (float*)d_out;                       // [2,2048,512]
    float* att = out + (long long)NTOK * DM;          // [2,8,2048,2048]

    float *F, *Kpart, *ks, *Spart, *S;
    __half *XH, *XL, *WH, *WL, *Qnh, *Qnl, *Knh, *OHh, *OHl;
    cudaGetSymbolAddress((void**)&F, g_F);
    cudaGetSymbolAddress((void**)&Kpart, g_Kpart);
    cudaGetSymbolAddress((void**)&ks, g_ksum);
    cudaGetSymbolAddress((void**)&Spart, g_Spart);
    cudaGetSymbolAddress((void**)&S, g_S);
    cudaGetSymbolAddress((void**)&XH, g_XH);  cudaGetSymbolAddress((void**)&XL, g_XL);
    cudaGetSymbolAddress((void**)&WH, g_WH);  cudaGetSymbolAddress((void**)&WL, g_WL);
    cudaGetSymbolAddress((void**)&Qnh, g_Qnh); cudaGetSymbolAddress((void**)&Qnl, g_Qnl);
    cudaGetSymbolAddress((void**)&Knh, g_Knh);
    cudaGetSymbolAddress((void**)&OHh, g_OHh); cudaGetSymbolAddress((void**)&OHl, g_OHl);

    float* Qf = F;
    float* Kf = F + (long long)NTOK * DM;
    float* Vf = F + 2LL * NTOK * DM;

    constexpr int SM2 = 2 * 3 * TILEB;   // 61440 (2-term)
    constexpr int SM3 = 2 * 4 * TILEB;   // 81920 (3-term)
    cudaFuncSetAttribute(mm_kernel<2>, cudaFuncAttributeMaxDynamicSharedMemorySize, SM2);
    cudaFuncSetAttribute(mm_kernel<3>, cudaFuncAttributeMaxDynamicSharedMemorySize, SM3);

    // 0: one-time fp32 -> fp16 hi/lo conversions (inputs + weights)
    cvt3_kernel<<<dim3(2048, 3), 256>>>(q, k, v, XH, XL);
    cvt4_kernel<<<dim3(256, 4), 256>>>(Wq, Wk, Wv, Wo, WH, WL);

    // 1: batched projections q/k/v, 2-term (x exact, W hi); elu+1 fused for q,k
    mm_kernel<2><<<dim3(4, 32, 3), 256, SM2>>>(
        XH, XL, DM, WH, nullptr, DM, F, DM, DM,
        bq, bk, bv, 0b011, 0, 1.f, 1,
        (long long)NTOK * DM, 0, (long long)DM * DM, 0, (long long)NTOK * DM, 0);

    // 2: Qn (row-normalize per head) -> fp32 + fp16 hi/lo (x64)
    qnorm_kernel<<<NTOK / 2, 256>>>(Qf, Qnh, Qnl);

    // 3: Kn (column-normalize over sequence) -> fp32 + fp16 hi (x2048)
    ksum_part_kernel<<<dim3(16, 8), 128>>>(Kf, Kpart);
    ksum_reduce_kernel<<<1, 1024>>>(Kpart, ks);
    knorm_kernel<<<2048, 256>>>(Kf, ks, Knh);

    // 4: attention_weights = Qn @ Kn^T per (b,h), 2-term -> d_out att (streamed)
    mm_kernel<2><<<dim3(16, 16, 16), 256, SM2>>>(
        Qnh, Qnl, DM, Knh, nullptr, DM, att, NSEQ, DK,
        nullptr, nullptr, nullptr, 0, 1, ATT_CSCALE, NHEADS,
        (long long)NSEQ * DM, (long long)DK,
        (long long)NSEQ * DM, (long long)DK,
        (long long)NHEADS * NSEQ * NSEQ, (long long)NSEQ * NSEQ);

    // 5: out_heads = Qn @ (Kn^T V) -> fp16 hi/lo
    s_part_kernel<<<dim3(32, 16), 256>>>(Kf, Vf, Spart);
    s_reduce_kernel<<<64, 1024>>>(Spart, S);
    oh_kernel<<<dim3(16, 16), 256>>>(Qf, S, OHh, OHl);

    // 6: final projection, 3-term (direct output) -> d_out
    mm_kernel<3><<<dim3(4, 32, 1), 256, SM3>>>(
        OHh, OHl, DM, WH + 3LL * DM * DM, WL + 3LL * DM * DM, DM, out, DM, DM,
        bo, nullptr, nullptr, 0, 0, 1.f, 1,
        0, 0, 0, 0, 0, 0);
}

// round 7
// speedup vs baseline: 1.9122x; 1.1262x over previous
#include <cuda_runtime.h>
#include <cuda_fp16.h>
#include <cstdint>

#define NTOK   4096          // B*N = 2*2048
#define DM     512
#define NSEQ   2048
#define NHEADS 8
#define DK     64

#define QSCALE 64.0f
#define KSCALE 2048.0f
#define ATT_CSCALE (1.0f / (64.0f * 2048.0f))
#define OH_CSCALE  (1.0f / (64.0f * 2048.0f))

// ---------------- scratch (__device__ globals; no allocs allowed) ----------
__device__ float g_F[3 * NTOK * DM];                       // Qf,Kf,Vf fp32
__device__ __half g_XH[3 * NTOK * DM], g_XL[3 * NTOK * DM];   // q,k,v hi/lo
__device__ __half g_WH[4 * DM * DM],  g_WL[4 * DM * DM];      // Wq,Wk,Wv,Wo
__device__ __half g_Qnh[NTOK * DM], g_Qnl[NTOK * DM];         // Qn * 64 (exact pair)
__device__ __half g_Knh[NTOK * DM];                           // Kn * 2048 (hi only)
__device__ __half g_OHh[NTOK * DM], g_OHl[NTOK * DM];
__device__ float g_Kpart[16 * 1024];
__device__ float g_ksum[1024];
__device__ float g_Spart[32 * 16 * DK * DK];                  // scaled x2048
__device__ float g_S[16 * DK * DK];                           // scaled x2048

// ---------------- helpers ---------------------------------------------------
__device__ __forceinline__ void cvt_split(float x, __half& hi, __half& lo) {
    hi = __float2half_rn(x);
    lo = __float2half_rn(x - __half2float(hi));
}
__device__ __forceinline__ uint32_t pack2(__half a, __half b) {
    __half2 t(a, b);
    return *reinterpret_cast<uint32_t*>(&t);
}
__device__ __forceinline__ uint32_t smem_u32(const void* p) {
    uint32_t a;
    asm("{ .reg .u64 t; cvta.to.shared.u64 t, %1; cvt.u32.u64 %0, t; }" : "=r"(a) : "l"(p));
    return a;
}
__device__ __forceinline__ void mma16816(float* c, const uint32_t* a, const uint32_t* b) {
    asm volatile(
        "mma.sync.aligned.m16n8k16.row.col.f32.f16.f16.f32 "
        "{%0,%1,%2,%3},{%4,%5,%6,%7},{%8,%9},{%0,%1,%2,%3};"
        : "+f"(c[0]), "+f"(c[1]), "+f"(c[2]), "+f"(c[3])
        : "r"(a[0]), "r"(a[1]), "r"(a[2]), "r"(a[3]), "r"(b[0]), "r"(b[1]));
}
__device__ __forceinline__ void ldsm4(uint32_t* r, uint32_t a) {
    asm volatile("ldmatrix.sync.aligned.m8n8.x4.shared.b16 {%0,%1,%2,%3},[%4];"
                 : "=r"(r[0]), "=r"(r[1]), "=r"(r[2]), "=r"(r[3]) : "r"(a));
}

// ---------------- fp32 -> fp16 hi/lo conversion kernels ---------------------
__global__ void cvt3_kernel(const float* __restrict__ x0, const float* __restrict__ x1,
                            const float* __restrict__ x2,
                            __half* __restrict__ H, __half* __restrict__ L)
{
    int i = blockIdx.x * blockDim.x + threadIdx.x;
    const float* x = (blockIdx.y == 0) ? x0 : (blockIdx.y == 1) ? x1 : x2;
    long long off = (long long)blockIdx.y * (NTOK * DM / 4);
    float4 v = reinterpret_cast<const float4*>(x)[i];
    __half a, b, c, d, e, f, g, hh;
    cvt_split(v.x, a, e); cvt_split(v.y, b, f);
    cvt_split(v.z, c, g); cvt_split(v.w, d, hh);
    uint2 ph; ph.x = pack2(a, b); ph.y = pack2(c, d);
    uint2 pl; pl.x = pack2(e, f); pl.y = pack2(g, hh);
    reinterpret_cast<uint2*>(H)[off + i] = ph;
    reinterpret_cast<uint2*>(L)[off + i] = pl;
}

__global__ void cvt4_kernel(const float* __restrict__ x0, const float* __restrict__ x1,
                            const float* __restrict__ x2, const float* __restrict__ x3,
                            __half* __restrict__ H, __half* __restrict__ L)
{
    int i = blockIdx.x * blockDim.x + threadIdx.x;
    const float* x = x0;
    if (blockIdx.y == 1) x = x1; else if (blockIdx.y == 2) x = x2; else if (blockIdx.y == 3) x = x3;
    long long off = (long long)blockIdx.y * (DM * DM / 4);
    float4 v = reinterpret_cast<const float4*>(x)[i];
    __half a, b, c, d, e, f, g, hh;
    cvt_split(v.x, a, e); cvt_split(v.y, b, f);
    cvt_split(v.z, c, g); cvt_split(v.w, d, hh);
    uint2 ph; ph.x = pack2(a, b); ph.y = pack2(c, d);
    uint2 pl; pl.x = pack2(e, f); pl.y = pack2(g, hh);
    reinterpret_cast<uint2*>(H)[off + i] = ph;
    reinterpret_cast<uint2*>(L)[off + i] = pl;
}

// ---------------- generic ldmatrix-fed fp16 hi/lo GEMM ----------------------
#define GST   40                  // padded row: 32 elems + 8 (80B; LDSM conflict-free)
#define TILEB (128 * GST * 2)     // 10240 B per tile

template<int NT>
__global__ __launch_bounds__(256, 2)
void mm_kernel(const __half* __restrict__ Ahi, const __half* __restrict__ Alo,
               long long lda,
               const __half* __restrict__ Bhi, const __half* __restrict__ Blo,
               long long ldb,
               float* __restrict__ C, long long ldc, int K,
               const float* __restrict__ b0, const float* __restrict__ b1,
               const float* __restrict__ b2,
               int actmask, int streamC, float cscale, int heads,
               long long sAb, long long sAh, long long sBb, long long sBh,
               long long sCb, long long sCh)
{
    extern __shared__ __half smem[];
    constexpr int NTILE  = NT + 1;            // Ahi, Alo, Bhi[, Blo]
    constexpr int STAGEB = NTILE * TILEB;

    int z = blockIdx.z, zb = z / heads, zh = z - zb * heads;
    Ahi += zb * sAb + zh * sAh;  Alo += zb * sAb + zh * sAh;
    Bhi += zb * sBb + zh * sBh;  if (NT == 3) Blo += zb * sBb + zh * sBh;
    C   += zb * sCb + zh * sCh;
    const float* bias = (zb == 0) ? b0 : (zb == 1) ? b1 : b2;
    int act = (actmask >> zb) & 1;

    int m0 = blockIdx.y * 128, n0 = blockIdx.x * 128;
    int tid = threadIdx.x, lane = tid & 31, warp = tid >> 5;
    int wm = (warp >> 1) * 32;
    int wn = (warp & 1) * 64;
    int grp = lane >> 2, tig = lane & 3;
    uint32_t sb = smem_u32(smem);

    int aoff = (wm + (lane & 15)) * GST + ((lane >> 4) << 3);
    int boff = (wn + ((lane >> 4) << 3) + (lane & 7)) * GST + (((lane >> 3) & 1) << 3);

    float acc[2][8][4];
    #pragma unroll
    for (int i = 0; i < 2; i++)
        #pragma unroll
        for (int j = 0; j < 8; j++)
            #pragma unroll
            for (int l = 0; l < 4; l++) acc[i][j][l] = 0.f;

    auto issue = [&](int s, int kt) {
        #pragma unroll
        for (int j = 0; j < 2 * NTILE; j++) {
            int id = tid + j * 256;
            int tile = id >> 9;
            int w = id & 511;
            int r = w >> 2, ce = (w & 3) * 8;
            const __half* src;
            if (tile == 0)      src = Ahi + (long long)(m0 + r) * lda + kt + ce;
            else if (tile == 1) src = Alo + (long long)(m0 + r) * lda + kt + ce;
            else if (tile == 2) src = Bhi + (long long)(n0 + r) * ldb + kt + ce;
            else                src = Blo + (long long)(n0 + r) * ldb + kt + ce;
            uint32_t d = sb + (uint32_t)(s * STAGEB + tile * TILEB) + (uint32_t)(r * GST + ce) * 2u;
            asm volatile("cp.async.cg.shared.global [%0],[%1],16;\n" :: "r"(d), "l"(src));
        }
        asm volatile("cp.async.commit_group;\n" ::);
    };

    int nt = K >> 5;
    issue(0, 0);
    for (int i = 0; i < nt; i++) {
        int cur = i & 1;
        if (i + 1 < nt) {
            issue(cur ^ 1, (i + 1) << 5);
            asm volatile("cp.async.wait_group 1;\n" ::);
        } else {
            asm volatile("cp.async.wait_group 0;\n" ::);
        }
        __syncthreads();
        uint32_t sA  = sb + cur * STAGEB;
        uint32_t sAl = sA + TILEB;
        uint32_t sB  = sA + 2 * TILEB;
        uint32_t sBl = sA + 3 * TILEB;

        #pragma unroll
        for (int kk = 0; kk < 32; kk += 16) {
            uint32_t ah[2][4], al[2][4], bf[4][4];
            #pragma unroll
            for (int mi = 0; mi < 2; mi++)
                ldsm4(ah[mi], sA + (uint32_t)(aoff + mi * 16 * GST + kk) * 2u);
            #pragma unroll
            for (int n2 = 0; n2 < 4; n2++)
                ldsm4(bf[n2], sB + (uint32_t)(boff + n2 * 16 * GST + kk) * 2u);
            #pragma unroll
            for (int mi = 0; mi < 2; mi++)
                #pragma unroll
                for (int n2 = 0; n2 < 4; n2++) {
                    mma16816(acc[mi][2 * n2],     ah[mi], bf[n2]);
                    mma16816(acc[mi][2 * n2 + 1], ah[mi], bf[n2] + 2);
                }
            #pragma unroll
            for (int mi = 0; mi < 2; mi++)
                ldsm4(al[mi], sAl + (uint32_t)(aoff + mi * 16 * GST + kk) * 2u);
            #pragma unroll
            for (int mi = 0; mi < 2; mi++)
                #pragma unroll
                for (int n2 = 0; n2 < 4; n2++) {
                    mma16816(acc[mi][2 * n2],     al[mi], bf[n2]);
                    mma16816(acc[mi][2 * n2 + 1], al[mi], bf[n2] + 2);
                }
            if (NT == 3) {
                #pragma unroll
                for (int n2 = 0; n2 < 4; n2++)
                    ldsm4(bf[n2], sBl + (uint32_t)(boff + n2 * 16 * GST + kk) * 2u);
                #pragma unroll
                for (int mi = 0; mi < 2; mi++)
                    #pragma unroll
                    for (int n2 = 0; n2 < 4; n2++) {
                        mma16816(acc[mi][2 * n2],     ah[mi], bf[n2]);
                        mma16816(acc[mi][2 * n2 + 1], ah[mi], bf[n2] + 2);
                    }
            }
        }
        __syncthreads();
    }

    #pragma unroll
    for (int mi = 0; mi < 2; mi++) {
        #pragma unroll
        for (int ni = 0; ni < 8; ni++) {
            int row = m0 + wm + mi * 16 + grp;
            int col = n0 + wn + ni * 8 + tig * 2;
            float bb0 = 0.f, bb1 = 0.f;
            if (bias) { bb0 = __ldg(&bias[col]); bb1 = __ldg(&bias[col + 1]); }
            float v0 = acc[mi][ni][0] * cscale + bb0;
            float v1 = acc[mi][ni][1] * cscale + bb1;
            float v2 = acc[mi][ni][2] * cscale + bb0;
            float v3 = acc[mi][ni][3] * cscale + bb1;
            if (act) {
                v0 = (v0 > 0.f) ? v0 + 1.f : expf(v0);
                v1 = (v1 > 0.f) ? v1 + 1.f : expf(v1);
                v2 = (v2 > 0.f) ? v2 + 1.f : expf(v2);
                v3 = (v3 > 0.f) ? v3 + 1.f : expf(v3);
            }
            float2* a0 = reinterpret_cast<float2*>(C + (long long)row * ldc + col);
            float2* a1 = reinterpret_cast<float2*>(C + (long long)(row + 8) * ldc + col);
            float2 p0 = make_float2(v0, v1);
            float2 p1 = make_float2(v2, v3);
            if (streamC) { __stcs(a0, p0); __stcs(a1, p1); }
            else { *a0 = p0; *a1 = p1; }
        }
    }
}

// ---------------- fused: att (1-term fp16) + s_part (fp32 SIMT) -------------
// grid (16,16,18): z in {0,1} -> s_part (512 blocks), z in [2,18) -> att head z-2.
// att: C = ATT_CSCALE * Qnh @ Knh^T per (b,h), streamed to gmem.
// s_part: Spart[chunk,bh] = sum over 64-row chunk of Kn^T V (Kn from Knh, x2048).
#define ATT_SMEM (2 * 2 * TILEB)   // 40960 B (2 stages x {Ahi,Bhi})

__global__ __launch_bounds__(256, 2)
void att_spart_kernel(const __half* __restrict__ Qnh, const __half* __restrict__ Knh,
                      const float* __restrict__ Vf,
                      float* __restrict__ att, float* __restrict__ Spart)
{
    extern __shared__ char dsm[];
    int tid = threadIdx.x;

    if (blockIdx.z < 2) {
        // ---------------- s_part path ----------------
        float* Kt = reinterpret_cast<float*>(dsm);            // [64][64]
        float* Vt = Kt + 64 * 64;                             // [64][64]
        int id = blockIdx.x + blockIdx.y * 16 + blockIdx.z * 256;  // [0,512)
        int chunk = id & 31, bh = id >> 5;
        int b = bh >> 3, h = bh & 7;
        int d = tid & 63, qq = tid >> 6;
        float acc[16];
        #pragma unroll
        for (int j = 0; j < 16; j++) acc[j] = 0.f;
        long long base = ((long long)b * NSEQ + chunk * 64) * DM + h * DK;
        #pragma unroll
        for (int j = 0; j < 16; j++) {
            int idd = tid + j * 256;
            int nl = idd >> 6, dd = idd & 63;
            Kt[nl * 64 + dd] = __half2float(Knh[base + (long long)nl * DM + dd]);
            Vt[nl * 64 + dd] = Vf[base + (long long)nl * DM + dd];
        }
        __syncthreads();
        for (int nn = 0; nn < 64; nn++) {
            float kv = Kt[nn * 64 + d];
            const float4* vr = reinterpret_cast<const float4*>(&Vt[nn * 64 + qq * 16]);
            #pragma unroll
            for (int j4 = 0; j4 < 4; j4++) {
                float4 v = vr[j4];
                acc[j4 * 4 + 0] += kv * v.x;
                acc[j4 * 4 + 1] += kv * v.y;
                acc[j4 * 4 + 2] += kv * v.z;
                acc[j4 * 4 + 3] += kv * v.w;
            }
        }
        float* o = Spart + ((long long)chunk * 16 + bh) * (DK * DK) + d * DK + qq * 16;
        #pragma unroll
        for (int j4 = 0; j4 < 4; j4++)
            reinterpret_cast<float4*>(o)[j4] =
                make_float4(acc[j4 * 4], acc[j4 * 4 + 1], acc[j4 * 4 + 2], acc[j4 * 4 + 3]);
        return;
    }

    // ---------------- att path (1-term GEMM, K=64) ----------------
    int bh = blockIdx.z - 2;
    int b = bh >> 3, h = bh & 7;
    const __half* A = Qnh + (long long)b * NSEQ * DM + h * DK;
    const __half* B = Knh + (long long)b * NSEQ * DM + h * DK;
    float* C = att + (long long)bh * NSEQ * NSEQ;

    int m0 = blockIdx.y * 128, n0 = blockIdx.x * 128;
    int lane = tid & 31, warp = tid >> 5;
    int wm = (warp >> 1) * 32;
    int wn = (warp & 1) * 64;
    int grp = lane >> 2, tig = lane & 3;
    uint32_t sb = smem_u32(dsm);
    constexpr int STAGEB = 2 * TILEB;

    int aoff = (wm + (lane & 15)) * GST + ((lane >> 4) << 3);
    int boff = (wn + ((lane >> 4) << 3) + (lane & 7)) * GST + (((lane >> 3) & 1) << 3);

    float acc[2][8][4];
    #pragma unroll
    for (int i = 0; i < 2; i++)
        #pragma unroll
        for (int j = 0; j < 8; j++)
            #pragma unroll
            for (int l = 0; l < 4; l++) acc[i][j][l] = 0.f;

    auto issue = [&](int s, int kt) {
        #pragma unroll
        for (int j = 0; j < 4; j++) {
            int id = tid + j * 256;
            int tile = id >> 9;
            int w = id & 511;
            int r = w >> 2, ce = (w & 3) * 8;
            const __half* src = (tile == 0)
                ? A + (long long)(m0 + r) * DM + kt + ce
                : B + (long long)(n0 + r) * DM + kt + ce;
            uint32_t d = sb + (uint32_t)(s * STAGEB + tile * TILEB) + (uint32_t)(r * GST + ce) * 2u;
            asm volatile("cp.async.cg.shared.global [%0],[%1],16;\n" :: "r"(d), "l"(src));
        }
        asm volatile("cp.async.commit_group;\n" ::);
    };

    issue(0, 0);
    #pragma unroll
    for (int i = 0; i < 2; i++) {
        if (i == 0) {
            issue(1, 32);
            asm volatile("cp.async.wait_group 1;\n" ::);
        } else {
            asm volatile("cp.async.wait_group 0;\n" ::);
        }
        __syncthreads();
        uint32_t sA = sb + i * STAGEB;
        uint32_t sB = sA + TILEB;
        #pragma unroll
        for (int kk = 0; kk < 32; kk += 16) {
            uint32_t ah[2][4], bf[4][4];
            #pragma unroll
            for (int mi = 0; mi < 2; mi++)
                ldsm4(ah[mi], sA + (uint32_t)(aoff + mi * 16 * GST + kk) * 2u);
            #pragma unroll
            for (int n2 = 0; n2 < 4; n2++)
                ldsm4(bf[n2], sB + (uint32_t)(boff + n2 * 16 * GST + kk) * 2u);
            #pragma unroll
            for (int mi = 0; mi < 2; mi++)
                #pragma unroll
                for (int n2 = 0; n2 < 4; n2++) {
                    mma16816(acc[mi][2 * n2],     ah[mi], bf[n2]);
                    mma16816(acc[mi][2 * n2 + 1], ah[mi], bf[n2] + 2);
                }
        }
        __syncthreads();
    }

    #pragma unroll
    for (int mi = 0; mi < 2; mi++) {
        #pragma unroll
        for (int ni = 0; ni < 8; ni++) {
            int row = m0 + wm + mi * 16 + grp;
            int col = n0 + wn + ni * 8 + tig * 2;
            float2 p0 = make_float2(acc[mi][ni][0] * ATT_CSCALE, acc[mi][ni][1] * ATT_CSCALE);
            float2 p1 = make_float2(acc[mi][ni][2] * ATT_CSCALE, acc[mi][ni][3] * ATT_CSCALE);
            __stcs(reinterpret_cast<float2*>(C + (long long)row * NSEQ + col), p0);
            __stcs(reinterpret_cast<float2*>(C + (long long)(row + 8) * NSEQ + col), p1);
        }
    }
}

// ---------------- normalization kernels -------------------------------------
// qnorm: 256 thr = 2 rows x 128 thr (float4 each); head = 16 threads
__global__ void qnorm_kernel(const float* __restrict__ Q,
                             __half* __restrict__ Qh, __half* __restrict__ Ql) {
    int t = threadIdx.x;
    int r = t >> 7, c4 = t & 127;
    long long row = blockIdx.x * 2 + r;
    long long i4 = row * 128 + c4;
    float4 v = reinterpret_cast<const float4*>(Q)[i4];
    float s = v.x + v.y + v.z + v.w;
    #pragma unroll
    for (int o = 8; o > 0; o >>= 1) s += __shfl_xor_sync(0xffffffffu, s, o);
    float inv = QSCALE / (s + 1e-8f);
    __half h0, h1, h2, h3, l0, l1, l2, l3;
    cvt_split(v.x * inv, h0, l0); cvt_split(v.y * inv, h1, l1);
    cvt_split(v.z * inv, h2, l2); cvt_split(v.w * inv, h3, l3);
    uint2 ph; ph.x = pack2(h0, h1); ph.y = pack2(h2, h3);
    uint2 pl; pl.x = pack2(l0, l1); pl.y = pack2(l2, l3);
    reinterpret_cast<uint2*>(Qh)[i4] = ph;
    reinterpret_cast<uint2*>(Ql)[i4] = pl;
}

__global__ void ksum_part_kernel(const float* __restrict__ K, float* __restrict__ Kpart) {
    int chunk = blockIdx.x;
    int bd = blockIdx.y;
    int b = bd >> 2;
    int d = (bd & 3) * 128 + threadIdx.x;
    long long base = ((long long)b * NSEQ + chunk * 128) * DM + d;
    float s = 0.f;
    #pragma unroll 8
    for (int n = 0; n < 128; n++) s += K[base + (long long)n * DM];
    Kpart[chunk * 1024 + b * DM + d] = s;
}

__global__ void ksum_reduce_kernel(const float* __restrict__ Kpart, float* __restrict__ ks) {
    int t = threadIdx.x;
    float s = 0.f;
    #pragma unroll
    for (int c = 0; c < 16; c++) s += Kpart[c * 1024 + t];
    ks[t] = s;
}

// knorm: float4 per thread; writes Kn*2048 fp16 only
__global__ void knorm_kernel(const float* __restrict__ K, const float* __restrict__ ks,
                             __half* __restrict__ Kh) {
    long long i4 = (long long)blockIdx.x * blockDim.x + threadIdx.x;
    long long row = i4 >> 7;
    int b = (int)(row >> 11);
    int c4 = (int)(i4 & 127);
    float4 sv = reinterpret_cast<const float4*>(ks + b * DM)[c4];
    float4 v = reinterpret_cast<const float4*>(K)[i4];
    uint2 ph;
    ph.x = pack2(__float2half_rn(v.x * KSCALE / (sv.x + 1e-8f)),
                 __float2half_rn(v.y * KSCALE / (sv.y + 1e-8f)));
    ph.y = pack2(__float2half_rn(v.z * KSCALE / (sv.z + 1e-8f)),
                 __float2half_rn(v.w * KSCALE / (sv.w + 1e-8f)));
    reinterpret_cast<uint2*>(Kh)[i4] = ph;
}

__global__ void s_reduce_kernel(const float* __restrict__ Spart, float* __restrict__ S) {
    int i = blockIdx.x * 1024 + threadIdx.x;
    float s = 0.f;
    #pragma unroll
    for (int c = 0; c < 32; c++) s += Spart[(long long)c * 65536 + i];
    S[i] = s;
}

// ---------------- OH = Qn @ S per (b,h); reads Qnh+Qnl; writes fp16 hi/lo ---
__global__ void oh_kernel(const __half* __restrict__ Qnh, const __half* __restrict__ Qnl,
                          const float* __restrict__ S,
                          __half* __restrict__ OHh, __half* __restrict__ OHl) {
    int mc = blockIdx.x;
    int bh = blockIdx.y;
    int b = bh >> 3, h = bh & 7;
    int t = threadIdx.x;
    int e4 = t & 15, r = t >> 4;
    __shared__ float Ss[64][64];
    __shared__ float Qs[16][64];
    #pragma unroll
    for (int j = 0; j < 16; j++) {
        int id = t + j * 256;
        Ss[id >> 6][id & 63] = S[(long long)bh * (DK * DK) + id];
    }
    for (int it = 0; it < 8; it++) {
        int mrow = mc * 128 + it * 16;
        __syncthreads();
        #pragma unroll
        for (int j = 0; j < 4; j++) {
            int id = t + j * 256;
            int rr = id >> 6, dd = id & 63;
            long long qidx = ((long long)b * NSEQ + mrow + rr) * DM + h * DK + dd;
            Qs[rr][dd] = __half2float(Qnh[qidx]) + __half2float(Qnl[qidx]);
        }
        __syncthreads();
        float4 a = make_float4(0.f, 0.f, 0.f, 0.f);
        #pragma unroll
        for (int dd = 0; dd < 64; dd++) {
            float qd = Qs[r][dd];
            float4 s4 = *reinterpret_cast<const float4*>(&Ss[dd][e4 * 4]);
            a.x += qd * s4.x; a.y += qd * s4.y; a.z += qd * s4.z; a.w += qd * s4.w;
        }
        __half h0, h1, h2, h3, l0, l1, l2, l3;
        cvt_split(a.x * OH_CSCALE, h0, l0); cvt_split(a.y * OH_CSCALE, h1, l1);
        cvt_split(a.z * OH_CSCALE, h2, l2); cvt_split(a.w * OH_CSCALE, h3, l3);
        long long oidx = ((long long)b * NSEQ + mrow + r) * DM + h * DK + e4 * 4;
        uint2 ph; ph.x = pack2(h0, h1); ph.y = pack2(h2, h3);
        uint2 pl; pl.x = pack2(l0, l1); pl.y = pack2(l2, l3);
        *reinterpret_cast<uint2*>(OHh + oidx) = ph;
        *reinterpret_cast<uint2*>(OHl + oidx) = pl;
    }
}

// ---------------- launch ----------------------------------------------------
extern "C" void kernel_launch(void* const* d_in, const int* in_sizes, int n_in,
                              void* d_out, int out_size) {
    const float* q  = (const float*)d_in[0];
    const float* k  = (const float*)d_in[1];
    const float* v  = (const float*)d_in[2];
    const float* Wq = (const float*)d_in[3];
    const float* bq = (const float*)d_in[4];
    const float* Wk = (const float*)d_in[5];
    const float* bk = (const float*)d_in[6];
    const float* Wv = (const float*)d_in[7];
    const float* bv = (const float*)d_in[8];
    const float* Wo = (const float*)d_in[9];
    const float* bo = (const float*)d_in[10];

    float* out = (float*)d_out;                       // [2,2048,512]
    float* att = out + (long long)NTOK * DM;          // [2,8,2048,2048]

    float *F, *Kpart, *ks, *Spart, *S;
    __half *XH, *XL, *WH, *WL, *Qnh, *Qnl, *Knh, *OHh, *OHl;
    cudaGetSymbolAddress((void**)&F, g_F);
    cudaGetSymbolAddress((void**)&Kpart, g_Kpart);
    cudaGetSymbolAddress((void**)&ks, g_ksum);
    cudaGetSymbolAddress((void**)&Spart, g_Spart);
    cudaGetSymbolAddress((void**)&S, g_S);
    cudaGetSymbolAddress((void**)&XH, g_XH);  cudaGetSymbolAddress((void**)&XL, g_XL);
    cudaGetSymbolAddress((void**)&WH, g_WH);  cudaGetSymbolAddress((void**)&WL, g_WL);
    cudaGetSymbolAddress((void**)&Qnh, g_Qnh); cudaGetSymbolAddress((void**)&Qnl, g_Qnl);
    cudaGetSymbolAddress((void**)&Knh, g_Knh);
    cudaGetSymbolAddress((void**)&OHh, g_OHh); cudaGetSymbolAddress((void**)&OHl, g_OHl);

    float* Qf = F;
    float* Kf = F + (long long)NTOK * DM;
    float* Vf = F + 2LL * NTOK * DM;

    constexpr int SM2 = 2 * 3 * TILEB;   // 61440 (2-term)
    constexpr int SM3 = 2 * 4 * TILEB;   // 81920 (3-term)
    cudaFuncSetAttribute(mm_kernel<2>, cudaFuncAttributeMaxDynamicSharedMemorySize, SM2);
    cudaFuncSetAttribute(mm_kernel<3>, cudaFuncAttributeMaxDynamicSharedMemorySize, SM3);
    cudaFuncSetAttribute(att_spart_kernel, cudaFuncAttributeMaxDynamicSharedMemorySize, ATT_SMEM);

    // 0: one-time fp32 -> fp16 hi/lo conversions (inputs + weights)
    cvt3_kernel<<<dim3(2048, 3), 256>>>(q, k, v, XH, XL);
    cvt4_kernel<<<dim3(256, 4), 256>>>(Wq, Wk, Wv, Wo, WH, WL);

    // 1: batched projections q/k/v, 2-term (x exact, W hi); elu+1 fused for q,k
    mm_kernel<2><<<dim3(4, 32, 3), 256, SM2>>>(
        XH, XL, DM, WH, nullptr, DM, F, DM, DM,
        bq, bk, bv, 0b011, 0, 1.f, 1,
        (long long)NTOK * DM, 0, (long long)DM * DM, 0, (long long)NTOK * DM, 0);

    // 2: Qn (row-normalize per head) -> fp16 hi/lo (x64)
    qnorm_kernel<<<NTOK / 2, 256>>>(Qf, Qnh, Qnl);

    // 3: Kn (column-normalize over sequence) -> fp16 hi (x2048)
    ksum_part_kernel<<<dim3(16, 8), 128>>>(Kf, Kpart);
    ksum_reduce_kernel<<<1, 1024>>>(Kpart, ks);
    knorm_kernel<<<2048, 256>>>(Kf, ks, Knh);

    // 4: fused att (1-term, streamed) + s_part (overlapped, z=0,1)
    att_spart_kernel<<<dim3(16, 16, 18), 256, ATT_SMEM>>>(Qnh, Knh, Vf, att, Spart);

    // 5: S reduce, then OH = Qn @ S -> fp16 hi/lo
    s_reduce_kernel<<<64, 1024>>>(Spart, S);
    oh_kernel<<<dim3(16, 16), 256>>>(Qnh, Qnl, S, OHh, OHl);

    // 6: final projection, 3-term (direct output) -> d_out
    mm_kernel<3><<<dim3(4, 32, 1), 256, SM3>>>(
        OHh, OHl, DM, WH + 3LL * DM * DM, WL + 3LL * DM * DM, DM, out, DM, DM,
        bo, nullptr, nullptr, 0, 0, 1.f, 1,
        0, 0, 0, 0, 0, 0);
}

// round 8
// speedup vs baseline: 2.0636x; 1.0792x over previous
#include <cuda_runtime.h>
#include <cuda_fp16.h>
#include <cstdint>

#define NTOK   4096          // B*N = 2*2048
#define DM     512
#define NSEQ   2048
#define NHEADS 8
#define DK     64

#define QSCALE 64.0f
#define KSCALE 2048.0f
#define ATT_CSCALE (1.0f / (64.0f * 2048.0f))
#define OH_CSCALE  (1.0f / (64.0f * 2048.0f))

// ---------------- scratch (__device__ globals; no allocs allowed) ----------
__device__ float g_Vf[NTOK * DM];                             // V fp32
__device__ __half g_XH[3 * NTOK * DM], g_XL[3 * NTOK * DM];   // q,k,v hi/lo
__device__ __half g_WH[4 * DM * DM],  g_WL[4 * DM * DM];      // Wq,Wk,Wv,Wo
__device__ __half g_Qnh[NTOK * DM], g_Qnl[NTOK * DM];         // Qn * 64 (exact pair)
__device__ __half g_Kh[NTOK * DM];                            // elu(K)+1, fp16
__device__ __half g_Knh[NTOK * DM];                           // Kn * 2048
__device__ __half g_OHh[NTOK * DM], g_OHl[NTOK * DM];
__device__ float g_ksum[1024];                                // per (b, d) col sums
__device__ float g_Spart[32 * 16 * DK * DK];                  // scaled x2048
__device__ float g_S[16 * DK * DK];                           // scaled x2048

// ---------------- helpers ---------------------------------------------------
__device__ __forceinline__ void cvt_split(float x, __half& hi, __half& lo) {
    hi = __float2half_rn(x);
    lo = __float2half_rn(x - __half2float(hi));
}
__device__ __forceinline__ uint32_t pack2(__half a, __half b) {
    __half2 t(a, b);
    return *reinterpret_cast<uint32_t*>(&t);
}
__device__ __forceinline__ uint32_t smem_u32(const void* p) {
    uint32_t a;
    asm("{ .reg .u64 t; cvta.to.shared.u64 t, %1; cvt.u32.u64 %0, t; }" : "=r"(a) : "l"(p));
    return a;
}
__device__ __forceinline__ void mma16816(float* c, const uint32_t* a, const uint32_t* b) {
    asm volatile(
        "mma.sync.aligned.m16n8k16.row.col.f32.f16.f16.f32 "
        "{%0,%1,%2,%3},{%4,%5,%6,%7},{%8,%9},{%0,%1,%2,%3};"
        : "+f"(c[0]), "+f"(c[1]), "+f"(c[2]), "+f"(c[3])
        : "r"(a[0]), "r"(a[1]), "r"(a[2]), "r"(a[3]), "r"(b[0]), "r"(b[1]));
}
__device__ __forceinline__ void ldsm4(uint32_t* r, uint32_t a) {
    asm volatile("ldmatrix.sync.aligned.m8n8.x4.shared.b16 {%0,%1,%2,%3},[%4];"
                 : "=r"(r[0]), "=r"(r[1]), "=r"(r[2]), "=r"(r[3]) : "r"(a));
}
__device__ __forceinline__ float elup1(float x) {
    return (x > 0.f) ? x + 1.f : expf(x);
}

// ---------------- fp32 -> fp16 hi/lo conversion kernels ---------------------
__global__ void cvt3_kernel(const float* __restrict__ x0, const float* __restrict__ x1,
                            const float* __restrict__ x2,
                            __half* __restrict__ H, __half* __restrict__ L,
                            float* __restrict__ ksum)
{
    // zero ksum each launch (blocks y==0, x<4)
    if (blockIdx.y == 0 && blockIdx.x < 4)
        ksum[blockIdx.x * 256 + threadIdx.x] = 0.f;
    int i = blockIdx.x * blockDim.x + threadIdx.x;
    const float* x = (blockIdx.y == 0) ? x0 : (blockIdx.y == 1) ? x1 : x2;
    long long off = (long long)blockIdx.y * (NTOK * DM / 4);
    float4 v = reinterpret_cast<const float4*>(x)[i];
    __half a, b, c, d, e, f, g, hh;
    cvt_split(v.x, a, e); cvt_split(v.y, b, f);
    cvt_split(v.z, c, g); cvt_split(v.w, d, hh);
    uint2 ph; ph.x = pack2(a, b); ph.y = pack2(c, d);
    uint2 pl; pl.x = pack2(e, f); pl.y = pack2(g, hh);
    reinterpret_cast<uint2*>(H)[off + i] = ph;
    reinterpret_cast<uint2*>(L)[off + i] = pl;
}

__global__ void cvt4_kernel(const float* __restrict__ x0, const float* __restrict__ x1,
                            const float* __restrict__ x2, const float* __restrict__ x3,
                            __half* __restrict__ H, __half* __restrict__ L)
{
    int i = blockIdx.x * blockDim.x + threadIdx.x;
    const float* x = x0;
    if (blockIdx.y == 1) x = x1; else if (blockIdx.y == 2) x = x2; else if (blockIdx.y == 3) x = x3;
    long long off = (long long)blockIdx.y * (DM * DM / 4);
    float4 v = reinterpret_cast<const float4*>(x)[i];
    __half a, b, c, d, e, f, g, hh;
    cvt_split(v.x, a, e); cvt_split(v.y, b, f);
    cvt_split(v.z, c, g); cvt_split(v.w, d, hh);
    uint2 ph; ph.x = pack2(a, b); ph.y = pack2(c, d);
    uint2 pl; pl.x = pack2(e, f); pl.y = pack2(g, hh);
    reinterpret_cast<uint2*>(H)[off + i] = ph;
    reinterpret_cast<uint2*>(L)[off + i] = pl;
}

// ---------------- shared GEMM plumbing --------------------------------------
#define GST   40                  // padded row: 32 elems + 8 (80B; LDSM conflict-free)
#define TILEB (128 * GST * 2)     // 10240 B per tile

// ---------------- fused projection kernel -----------------------------------
// z = 0,1,2 -> q,k,v. 2-term (x exact hi/lo, W hi). K=512.
// q: fused elu+1 + per-head row-normalize -> Qnh/Qnl (x64)
// k: fused elu+1 -> Kh fp16 + column-sum atomics into ksum
// v: plain -> Vf fp32
__global__ __launch_bounds__(256, 2)
void proj_kernel(const __half* __restrict__ XH, const __half* __restrict__ XL,
                 const __half* __restrict__ WH,
                 const float* __restrict__ bq, const float* __restrict__ bk,
                 const float* __restrict__ bv,
                 __half* __restrict__ Qnh, __half* __restrict__ Qnl,
                 __half* __restrict__ Kh, float* __restrict__ Vf,
                 float* __restrict__ ksum)
{
    extern __shared__ __half smem[];
    constexpr int STAGEB = 3 * TILEB;
    int zb = blockIdx.z;
    const __half* Ahi = XH + (long long)zb * NTOK * DM;
    const __half* Alo = XL + (long long)zb * NTOK * DM;
    const __half* Bhi = WH + (long long)zb * DM * DM;
    const float* bias = (zb == 0) ? bq : (zb == 1) ? bk : bv;

    int m0 = blockIdx.y * 128, n0 = blockIdx.x * 128;
    int tid = threadIdx.x, lane = tid & 31, warp = tid >> 5;
    int wm = (warp >> 1) * 32;
    int wn = (warp & 1) * 64;
    int grp = lane >> 2, tig = lane & 3;
    uint32_t sb = smem_u32(smem);

    int aoff = (wm + (lane & 15)) * GST + ((lane >> 4) << 3);
    int boff = (wn + ((lane >> 4) << 3) + (lane & 7)) * GST + (((lane >> 3) & 1) << 3);

    float acc[2][8][4];
    #pragma unroll
    for (int i = 0; i < 2; i++)
        #pragma unroll
        for (int j = 0; j < 8; j++)
            #pragma unroll
            for (int l = 0; l < 4; l++) acc[i][j][l] = 0.f;

    auto issue = [&](int s, int kt) {
        #pragma unroll
        for (int j = 0; j < 6; j++) {
            int id = tid + j * 256;
            int tile = id >> 9;
            int w = id & 511;
            int r = w >> 2, ce = (w & 3) * 8;
            const __half* src;
            if (tile == 0)      src = Ahi + (long long)(m0 + r) * DM + kt + ce;
            else if (tile == 1) src = Alo + (long long)(m0 + r) * DM + kt + ce;
            else                src = Bhi + (long long)(n0 + r) * DM + kt + ce;
            uint32_t d = sb + (uint32_t)(s * STAGEB + tile * TILEB) + (uint32_t)(r * GST + ce) * 2u;
            asm volatile("cp.async.cg.shared.global [%0],[%1],16;\n" :: "r"(d), "l"(src));
        }
        asm volatile("cp.async.commit_group;\n" ::);
    };

    issue(0, 0);
    for (int i = 0; i < 16; i++) {
        int cur = i & 1;
        if (i + 1 < 16) {
            issue(cur ^ 1, (i + 1) << 5);
            asm volatile("cp.async.wait_group 1;\n" ::);
        } else {
            asm volatile("cp.async.wait_group 0;\n" ::);
        }
        __syncthreads();
        uint32_t sA  = sb + cur * STAGEB;
        uint32_t sAl = sA + TILEB;
        uint32_t sB  = sA + 2 * TILEB;

        #pragma unroll
        for (int kk = 0; kk < 32; kk += 16) {
            uint32_t ah[2][4], al[2][4], bf[4][4];
            #pragma unroll
            for (int mi = 0; mi < 2; mi++)
                ldsm4(ah[mi], sA + (uint32_t)(aoff + mi * 16 * GST + kk) * 2u);
            #pragma unroll
            for (int n2 = 0; n2 < 4; n2++)
                ldsm4(bf[n2], sB + (uint32_t)(boff + n2 * 16 * GST + kk) * 2u);
            #pragma unroll
            for (int mi = 0; mi < 2; mi++)
                #pragma unroll
                for (int n2 = 0; n2 < 4; n2++) {
                    mma16816(acc[mi][2 * n2],     ah[mi], bf[n2]);
                    mma16816(acc[mi][2 * n2 + 1], ah[mi], bf[n2] + 2);
                }
            #pragma unroll
            for (int mi = 0; mi < 2; mi++)
                ldsm4(al[mi], sAl + (uint32_t)(aoff + mi * 16 * GST + kk) * 2u);
            #pragma unroll
            for (int mi = 0; mi < 2; mi++)
                #pragma unroll
                for (int n2 = 0; n2 < 4; n2++) {
                    mma16816(acc[mi][2 * n2],     al[mi], bf[n2]);
                    mma16816(acc[mi][2 * n2 + 1], al[mi], bf[n2] + 2);
                }
        }
        __syncthreads();
    }

    // ---- epilogue: bias (+ elu+1 for q,k) ----
    #pragma unroll
    for (int mi = 0; mi < 2; mi++)
        #pragma unroll
        for (int ni = 0; ni < 8; ni++) {
            int col = n0 + wn + ni * 8 + tig * 2;
            float bb0 = __ldg(&bias[col]), bb1 = __ldg(&bias[col + 1]);
            acc[mi][ni][0] += bb0; acc[mi][ni][1] += bb1;
            acc[mi][ni][2] += bb0; acc[mi][ni][3] += bb1;
            if (zb < 2) {
                acc[mi][ni][0] = elup1(acc[mi][ni][0]);
                acc[mi][ni][1] = elup1(acc[mi][ni][1]);
                acc[mi][ni][2] = elup1(acc[mi][ni][2]);
                acc[mi][ni][3] = elup1(acc[mi][ni][3]);
            }
        }

    if (zb == 0) {
        // Q: per-head row-normalize (warp's 64 cols = one full head)
        #pragma unroll
        for (int mi = 0; mi < 2; mi++) {
            float s0 = 0.f, s1 = 0.f;
            #pragma unroll
            for (int ni = 0; ni < 8; ni++) {
                s0 += acc[mi][ni][0] + acc[mi][ni][1];
                s1 += acc[mi][ni][2] + acc[mi][ni][3];
            }
            s0 += __shfl_xor_sync(0xffffffffu, s0, 1);
            s0 += __shfl_xor_sync(0xffffffffu, s0, 2);
            s1 += __shfl_xor_sync(0xffffffffu, s1, 1);
            s1 += __shfl_xor_sync(0xffffffffu, s1, 2);
            float inv0 = QSCALE / (s0 + 1e-8f);
            float inv1 = QSCALE / (s1 + 1e-8f);
            int r0 = m0 + wm + mi * 16 + grp;
            #pragma unroll
            for (int ni = 0; ni < 8; ni++) {
                int col = n0 + wn + ni * 8 + tig * 2;
                __half h0, l0, h1, l1;
                cvt_split(acc[mi][ni][0] * inv0, h0, l0);
                cvt_split(acc[mi][ni][1] * inv0, h1, l1);
                *reinterpret_cast<uint32_t*>(&Qnh[(long long)r0 * DM + col]) = pack2(h0, h1);
                *reinterpret_cast<uint32_t*>(&Qnl[(long long)r0 * DM + col]) = pack2(l0, l1);
                cvt_split(acc[mi][ni][2] * inv1, h0, l0);
                cvt_split(acc[mi][ni][3] * inv1, h1, l1);
                *reinterpret_cast<uint32_t*>(&Qnh[(long long)(r0 + 8) * DM + col]) = pack2(h0, h1);
                *reinterpret_cast<uint32_t*>(&Qnl[(long long)(r0 + 8) * DM + col]) = pack2(l0, l1);
            }
        }
    } else if (zb == 1) {
        // K: store fp16 + column-sum atomics
        int bb = m0 >> 11;
        #pragma unroll
        for (int ni = 0; ni < 8; ni++) {
            int col = n0 + wn + ni * 8 + tig * 2;
            float c0 = 0.f, c1 = 0.f;
            #pragma unroll
            for (int mi = 0; mi < 2; mi++) {
                int r0 = m0 + wm + mi * 16 + grp;
                c0 += acc[mi][ni][0] + acc[mi][ni][2];
                c1 += acc[mi][ni][1] + acc[mi][ni][3];
                *reinterpret_cast<uint32_t*>(&Kh[(long long)r0 * DM + col]) =
                    pack2(__float2half_rn(acc[mi][ni][0]), __float2half_rn(acc[mi][ni][1]));
                *reinterpret_cast<uint32_t*>(&Kh[(long long)(r0 + 8) * DM + col]) =
                    pack2(__float2half_rn(acc[mi][ni][2]), __float2half_rn(acc[mi][ni][3]));
            }
            c0 += __shfl_xor_sync(0xffffffffu, c0, 4);
            c0 += __shfl_xor_sync(0xffffffffu, c0, 8);
            c0 += __shfl_xor_sync(0xffffffffu, c0, 16);
            c1 += __shfl_xor_sync(0xffffffffu, c1, 4);
            c1 += __shfl_xor_sync(0xffffffffu, c1, 8);
            c1 += __shfl_xor_sync(0xffffffffu, c1, 16);
            if (grp == 0) {
                atomicAdd(&ksum[bb * DM + col], c0);
                atomicAdd(&ksum[bb * DM + col + 1], c1);
            }
        }
    } else {
        // V: fp32
        #pragma unroll
        for (int mi = 0; mi < 2; mi++)
            #pragma unroll
            for (int ni = 0; ni < 8; ni++) {
                int row = m0 + wm + mi * 16 + grp;
                int col = n0 + wn + ni * 8 + tig * 2;
                *reinterpret_cast<float2*>(Vf + (long long)row * DM + col) =
                    make_float2(acc[mi][ni][0], acc[mi][ni][1]);
                *reinterpret_cast<float2*>(Vf + (long long)(row + 8) * DM + col) =
                    make_float2(acc[mi][ni][2], acc[mi][ni][3]);
            }
    }
}

// ---------------- generic fp16 hi/lo GEMM (used for final projection) -------
template<int NT>
__global__ __launch_bounds__(256, 2)
void mm_kernel(const __half* __restrict__ Ahi, const __half* __restrict__ Alo,
               long long lda,
               const __half* __restrict__ Bhi, const __half* __restrict__ Blo,
               long long ldb,
               float* __restrict__ C, long long ldc, int K,
               const float* __restrict__ bias, int act, int streamC, float cscale)
{
    extern __shared__ __half smem[];
    constexpr int NTILE  = NT + 1;
    constexpr int STAGEB = NTILE * TILEB;

    int m0 = blockIdx.y * 128, n0 = blockIdx.x * 128;
    int tid = threadIdx.x, lane = tid & 31, warp = tid >> 5;
    int wm = (warp >> 1) * 32;
    int wn = (warp & 1) * 64;
    int grp = lane >> 2, tig = lane & 3;
    uint32_t sb = smem_u32(smem);

    int aoff = (wm + (lane & 15)) * GST + ((lane >> 4) << 3);
    int boff = (wn + ((lane >> 4) << 3) + (lane & 7)) * GST + (((lane >> 3) & 1) << 3);

    float acc[2][8][4];
    #pragma unroll
    for (int i = 0; i < 2; i++)
        #pragma unroll
        for (int j = 0; j < 8; j++)
            #pragma unroll
            for (int l = 0; l < 4; l++) acc[i][j][l] = 0.f;

    auto issue = [&](int s, int kt) {
        #pragma unroll
        for (int j = 0; j < 2 * NTILE; j++) {
            int id = tid + j * 256;
            int tile = id >> 9;
            int w = id & 511;
            int r = w >> 2, ce = (w & 3) * 8;
            const __half* src;
            if (tile == 0)      src = Ahi + (long long)(m0 + r) * lda + kt + ce;
            else if (tile == 1) src = Alo + (long long)(m0 + r) * lda + kt + ce;
            else if (tile == 2) src = Bhi + (long long)(n0 + r) * ldb + kt + ce;
            else                src = Blo + (long long)(n0 + r) * ldb + kt + ce;
            uint32_t d = sb + (uint32_t)(s * STAGEB + tile * TILEB) + (uint32_t)(r * GST + ce) * 2u;
            asm volatile("cp.async.cg.shared.global [%0],[%1],16;\n" :: "r"(d), "l"(src));
        }
        asm volatile("cp.async.commit_group;\n" ::);
    };

    int nt = K >> 5;
    issue(0, 0);
    for (int i = 0; i < nt; i++) {
        int cur = i & 1;
        if (i + 1 < nt) {
            issue(cur ^ 1, (i + 1) << 5);
            asm volatile("cp.async.wait_group 1;\n" ::);
        } else {
            asm volatile("cp.async.wait_group 0;\n" ::);
        }
        __syncthreads();
        uint32_t sA  = sb + cur * STAGEB;
        uint32_t sAl = sA + TILEB;
        uint32_t sB  = sA + 2 * TILEB;
        uint32_t sBl = sA + 3 * TILEB;

        #pragma unroll
        for (int kk = 0; kk < 32; kk += 16) {
            uint32_t ah[2][4], al[2][4], bf[4][4];
            #pragma unroll
            for (int mi = 0; mi < 2; mi++)
                ldsm4(ah[mi], sA + (uint32_t)(aoff + mi * 16 * GST + kk) * 2u);
            #pragma unroll
            for (int n2 = 0; n2 < 4; n2++)
                ldsm4(bf[n2], sB + (uint32_t)(boff + n2 * 16 * GST + kk) * 2u);
            #pragma unroll
            for (int mi = 0; mi < 2; mi++)
                #pragma unroll
                for (int n2 = 0; n2 < 4; n2++) {
                    mma16816(acc[mi][2 * n2],     ah[mi], bf[n2]);
                    mma16816(acc[mi][2 * n2 + 1], ah[mi], bf[n2] + 2);
                }
            #pragma unroll
            for (int mi = 0; mi < 2; mi++)
                ldsm4(al[mi], sAl + (uint32_t)(aoff + mi * 16 * GST + kk) * 2u);
            #pragma unroll
            for (int mi = 0; mi < 2; mi++)
                #pragma unroll
                for (int n2 = 0; n2 < 4; n2++) {
                    mma16816(acc[mi][2 * n2],     al[mi], bf[n2]);
                    mma16816(acc[mi][2 * n2 + 1], al[mi], bf[n2] + 2);
                }
            if (NT == 3) {
                #pragma unroll
                for (int n2 = 0; n2 < 4; n2++)
                    ldsm4(bf[n2], sBl + (uint32_t)(boff + n2 * 16 * GST + kk) * 2u);
                #pragma unroll
                for (int mi = 0; mi < 2; mi++)
                    #pragma unroll
                    for (int n2 = 0; n2 < 4; n2++) {
                        mma16816(acc[mi][2 * n2],     ah[mi], bf[n2]);
                        mma16816(acc[mi][2 * n2 + 1], ah[mi], bf[n2] + 2);
                    }
            }
        }
        __syncthreads();
    }

    #pragma unroll
    for (int mi = 0; mi < 2; mi++) {
        #pragma unroll
        for (int ni = 0; ni < 8; ni++) {
            int row = m0 + wm + mi * 16 + grp;
            int col = n0 + wn + ni * 8 + tig * 2;
            float bb0 = 0.f, bb1 = 0.f;
            if (bias) { bb0 = __ldg(&bias[col]); bb1 = __ldg(&bias[col + 1]); }
            float v0 = acc[mi][ni][0] * cscale + bb0;
            float v1 = acc[mi][ni][1] * cscale + bb1;
            float v2 = acc[mi][ni][2] * cscale + bb0;
            float v3 = acc[mi][ni][3] * cscale + bb1;
            if (act) { v0 = elup1(v0); v1 = elup1(v1); v2 = elup1(v2); v3 = elup1(v3); }
            float2* a0 = reinterpret_cast<float2*>(C + (long long)row * ldc + col);
            float2* a1 = reinterpret_cast<float2*>(C + (long long)(row + 8) * ldc + col);
            float2 p0 = make_float2(v0, v1);
            float2 p1 = make_float2(v2, v3);
            if (streamC) { __stcs(a0, p0); __stcs(a1, p1); }
            else { *a0 = p0; *a1 = p1; }
        }
    }
}

// ---------------- knorm: Knh = Kh * KSCALE / (ksum + eps) -------------------
__global__ void knorm_kernel(const __half* __restrict__ Kh, const float* __restrict__ ks,
                             __half* __restrict__ Knh) {
    long long i4 = (long long)blockIdx.x * blockDim.x + threadIdx.x;   // 4 halves each
    long long row = i4 >> 7;
    int b = (int)(row >> 11);
    int c4 = (int)(i4 & 127);
    float4 sv = reinterpret_cast<const float4*>(ks + b * DM)[c4];
    uint2 kv = reinterpret_cast<const uint2*>(Kh)[i4];
    __half2 k01 = *reinterpret_cast<__half2*>(&kv.x);
    __half2 k23 = *reinterpret_cast<__half2*>(&kv.y);
    uint2 ph;
    ph.x = pack2(__float2half_rn(__half2float(k01.x) * KSCALE / (sv.x + 1e-8f)),
                 __float2half_rn(__half2float(k01.y) * KSCALE / (sv.y + 1e-8f)));
    ph.y = pack2(__float2half_rn(__half2float(k23.x) * KSCALE / (sv.z + 1e-8f)),
                 __float2half_rn(__half2float(k23.y) * KSCALE / (sv.w + 1e-8f)));
    reinterpret_cast<uint2*>(Knh)[i4] = ph;
}

// ---------------- fused: att (1-term fp16) + s_part (fp32 SIMT) -------------
#define ATT_SMEM (2 * 2 * TILEB)   // 40960 B (2 stages x {Ahi,Bhi})

__global__ __launch_bounds__(256, 2)
void att_spart_kernel(const __half* __restrict__ Qnh, const __half* __restrict__ Knh,
                      const float* __restrict__ Vf,
                      float* __restrict__ att, float* __restrict__ Spart)
{
    extern __shared__ char dsm[];
    int tid = threadIdx.x;

    if (blockIdx.z < 2) {
        // ---------------- s_part path ----------------
        float* Kt = reinterpret_cast<float*>(dsm);            // [64][64]
        float* Vt = Kt + 64 * 64;                             // [64][64]
        int id = blockIdx.x + blockIdx.y * 16 + blockIdx.z * 256;  // [0,512)
        int chunk = id & 31, bh = id >> 5;
        int b = bh >> 3, h = bh & 7;
        int d = tid & 63, qq = tid >> 6;
        float acc[16];
        #pragma unroll
        for (int j = 0; j < 16; j++) acc[j] = 0.f;
        long long base = ((long long)b * NSEQ + chunk * 64) * DM + h * DK;
        #pragma unroll
        for (int j = 0; j < 16; j++) {
            int idd = tid + j * 256;
            int nl = idd >> 6, dd = idd & 63;
            Kt[nl * 64 + dd] = __half2float(Knh[base + (long long)nl * DM + dd]);
            Vt[nl * 64 + dd] = Vf[base + (long long)nl * DM + dd];
        }
        __syncthreads();
        for (int nn = 0; nn < 64; nn++) {
            float kv = Kt[nn * 64 + d];
            const float4* vr = reinterpret_cast<const float4*>(&Vt[nn * 64 + qq * 16]);
            #pragma unroll
            for (int j4 = 0; j4 < 4; j4++) {
                float4 v = vr[j4];
                acc[j4 * 4 + 0] += kv * v.x;
                acc[j4 * 4 + 1] += kv * v.y;
                acc[j4 * 4 + 2] += kv * v.z;
                acc[j4 * 4 + 3] += kv * v.w;
            }
        }
        float* o = Spart + ((long long)chunk * 16 + bh) * (DK * DK) + d * DK + qq * 16;
        #pragma unroll
        for (int j4 = 0; j4 < 4; j4++)
            reinterpret_cast<float4*>(o)[j4] =
                make_float4(acc[j4 * 4], acc[j4 * 4 + 1], acc[j4 * 4 + 2], acc[j4 * 4 + 3]);
        return;
    }

    // ---------------- att path (1-term GEMM, K=64) ----------------
    int bh = blockIdx.z - 2;
    int b = bh >> 3, h = bh & 7;
    const __half* A = Qnh + (long long)b * NSEQ * DM + h * DK;
    const __half* B = Knh + (long long)b * NSEQ * DM + h * DK;
    float* C = att + (long long)bh * NSEQ * NSEQ;

    int m0 = blockIdx.y * 128, n0 = blockIdx.x * 128;
    int lane = tid & 31, warp = tid >> 5;
    int wm = (warp >> 1) * 32;
    int wn = (warp & 1) * 64;
    int grp = lane >> 2, tig = lane & 3;
    uint32_t sb = smem_u32(dsm);
    constexpr int STAGEB = 2 * TILEB;

    int aoff = (wm + (lane & 15)) * GST + ((lane >> 4) << 3);
    int boff = (wn + ((lane >> 4) << 3) + (lane & 7)) * GST + (((lane >> 3) & 1) << 3);

    float acc[2][8][4];
    #pragma unroll
    for (int i = 0; i < 2; i++)
        #pragma unroll
        for (int j = 0; j < 8; j++)
            #pragma unroll
            for (int l = 0; l < 4; l++) acc[i][j][l] = 0.f;

    auto issue = [&](int s, int kt) {
        #pragma unroll
        for (int j = 0; j < 4; j++) {
            int id = tid + j * 256;
            int tile = id >> 9;
            int w = id & 511;
            int r = w >> 2, ce = (w & 3) * 8;
            const __half* src = (tile == 0)
                ? A + (long long)(m0 + r) * DM + kt + ce
                : B + (long long)(n0 + r) * DM + kt + ce;
            uint32_t d = sb + (uint32_t)(s * STAGEB + tile * TILEB) + (uint32_t)(r * GST + ce) * 2u;
            asm volatile("cp.async.cg.shared.global [%0],[%1],16;\n" :: "r"(d), "l"(src));
        }
        asm volatile("cp.async.commit_group;\n" ::);
    };

    issue(0, 0);
    #pragma unroll
    for (int i = 0; i < 2; i++) {
        if (i == 0) {
            issue(1, 32);
            asm volatile("cp.async.wait_group 1;\n" ::);
        } else {
            asm volatile("cp.async.wait_group 0;\n" ::);
        }
        __syncthreads();
        uint32_t sA = sb + i * STAGEB;
        uint32_t sB = sA + TILEB;
        #pragma unroll
        for (int kk = 0; kk < 32; kk += 16) {
            uint32_t ah[2][4], bf[4][4];
            #pragma unroll
            for (int mi = 0; mi < 2; mi++)
                ldsm4(ah[mi], sA + (uint32_t)(aoff + mi * 16 * GST + kk) * 2u);
            #pragma unroll
            for (int n2 = 0; n2 < 4; n2++)
                ldsm4(bf[n2], sB + (uint32_t)(boff + n2 * 16 * GST + kk) * 2u);
            #pragma unroll
            for (int mi = 0; mi < 2; mi++)
                #pragma unroll
                for (int n2 = 0; n2 < 4; n2++) {
                    mma16816(acc[mi][2 * n2],     ah[mi], bf[n2]);
                    mma16816(acc[mi][2 * n2 + 1], ah[mi], bf[n2] + 2);
                }
        }
        __syncthreads();
    }

    #pragma unroll
    for (int mi = 0; mi < 2; mi++) {
        #pragma unroll
        for (int ni = 0; ni < 8; ni++) {
            int row = m0 + wm + mi * 16 + grp;
            int col = n0 + wn + ni * 8 + tig * 2;
            float2 p0 = make_float2(acc[mi][ni][0] * ATT_CSCALE, acc[mi][ni][1] * ATT_CSCALE);
            float2 p1 = make_float2(acc[mi][ni][2] * ATT_CSCALE, acc[mi][ni][3] * ATT_CSCALE);
            __stcs(reinterpret_cast<float2*>(C + (long long)row * NSEQ + col), p0);
            __stcs(reinterpret_cast<float2*>(C + (long long)(row + 8) * NSEQ + col), p1);
        }
    }
}

__global__ void s_reduce_kernel(const float* __restrict__ Spart, float* __restrict__ S) {
    int i = blockIdx.x * 1024 + threadIdx.x;
    float s = 0.f;
    #pragma unroll
    for (int c = 0; c < 32; c++) s += Spart[(long long)c * 65536 + i];
    S[i] = s;
}

// ---------------- OH = Qn @ S per (b,h); reads Qnh+Qnl; writes fp16 hi/lo ---
__global__ void oh_kernel(const __half* __restrict__ Qnh, const __half* __restrict__ Qnl,
                          const float* __restrict__ S,
                          __half* __restrict__ OHh, __half* __restrict__ OHl) {
    int mc = blockIdx.x;
    int bh = blockIdx.y;
    int b = bh >> 3, h = bh & 7;
    int t = threadIdx.x;
    int e4 = t & 15, r = t >> 4;
    __shared__ float Ss[64][64];
    __shared__ float Qs[16][64];
    #pragma unroll
    for (int j = 0; j < 16; j++) {
        int id = t + j * 256;
        Ss[id >> 6][id & 63] = S[(long long)bh * (DK * DK) + id];
    }
    for (int it = 0; it < 8; it++) {
        int mrow = mc * 128 + it * 16;
        __syncthreads();
        #pragma unroll
        for (int j = 0; j < 4; j++) {
            int id = t + j * 256;
            int rr = id >> 6, dd = id & 63;
            long long qidx = ((long long)b * NSEQ + mrow + rr) * DM + h * DK + dd;
            Qs[rr][dd] = __half2float(Qnh[qidx]) + __half2float(Qnl[qidx]);
        }
        __syncthreads();
        float4 a = make_float4(0.f, 0.f, 0.f, 0.f);
        #pragma unroll
        for (int dd = 0; dd < 64; dd++) {
            float qd = Qs[r][dd];
            float4 s4 = *reinterpret_cast<const float4*>(&Ss[dd][e4 * 4]);
            a.x += qd * s4.x; a.y += qd * s4.y; a.z += qd * s4.z; a.w += qd * s4.w;
        }
        __half h0, h1, h2, h3, l0, l1, l2, l3;
        cvt_split(a.x * OH_CSCALE, h0, l0); cvt_split(a.y * OH_CSCALE, h1, l1);
        cvt_split(a.z * OH_CSCALE, h2, l2); cvt_split(a.w * OH_CSCALE, h3, l3);
        long long oidx = ((long long)b * NSEQ + mrow + r) * DM + h * DK + e4 * 4;
        uint2 ph; ph.x = pack2(h0, h1); ph.y = pack2(h2, h3);
        uint2 pl; pl.x = pack2(l0, l1); pl.y = pack2(l2, l3);
        *reinterpret_cast<uint2*>(OHh + oidx) = ph;
        *reinterpret_cast<uint2*>(OHl + oidx) = pl;
    }
}

// ---------------- launch ----------------------------------------------------
extern "C" void kernel_launch(void* const* d_in, const int* in_sizes, int n_in,
                              void* d_out, int out_size) {
    const float* q  = (const float*)d_in[0];
    const float* k  = (const float*)d_in[1];
    const float* v  = (const float*)d_in[2];
    const float* Wq = (const float*)d_in[3];
    const float* bq = (const float*)d_in[4];
    const float* Wk = (const float*)d_in[5];
    const float* bk = (const float*)d_in[6];
    const float* Wv = (const float*)d_in[7];
    const float* bv = (const float*)d_in[8];
    const float* Wo = (const float*)d_in[9];
    const float* bo = (const float*)d_in[10];

    float* out = (float*)d_out;                       // [2,2048,512]
    float* att = out + (long long)NTOK * DM;          // [2,8,2048,2048]

    float *Vf, *ks, *Spart, *S;
    __half *XH, *XL, *WH, *WL, *Qnh, *Qnl, *Kh, *Knh, *OHh, *OHl;
    cudaGetSymbolAddress((void**)&Vf, g_Vf);
    cudaGetSymbolAddress((void**)&ks, g_ksum);
    cudaGetSymbolAddress((void**)&Spart, g_Spart);
    cudaGetSymbolAddress((void**)&S, g_S);
    cudaGetSymbolAddress((void**)&XH, g_XH);  cudaGetSymbolAddress((void**)&XL, g_XL);
    cudaGetSymbolAddress((void**)&WH, g_WH);  cudaGetSymbolAddress((void**)&WL, g_WL);
    cudaGetSymbolAddress((void**)&Qnh, g_Qnh); cudaGetSymbolAddress((void**)&Qnl, g_Qnl);
    cudaGetSymbolAddress((void**)&Kh, g_Kh);   cudaGetSymbolAddress((void**)&Knh, g_Knh);
    cudaGetSymbolAddress((void**)&OHh, g_OHh); cudaGetSymbolAddress((void**)&OHl, g_OHl);

    constexpr int SMP  = 2 * 3 * TILEB;   // 61440 (proj / 2-term mm)
    cudaFuncSetAttribute(proj_kernel, cudaFuncAttributeMaxDynamicSharedMemorySize, SMP);
    cudaFuncSetAttribute(mm_kernel<2>, cudaFuncAttributeMaxDynamicSharedMemorySize, SMP);
    cudaFuncSetAttribute(att_spart_kernel, cudaFuncAttributeMaxDynamicSharedMemorySize, ATT_SMEM);

    // 0: one-time fp32 -> fp16 hi/lo conversions (+ zero ksum)
    cvt3_kernel<<<dim3(2048, 3), 256>>>(q, k, v, XH, XL, ks);
    cvt4_kernel<<<dim3(256, 4), 256>>>(Wq, Wk, Wv, Wo, WH, WL);

    // 1: fused projections: q->Qnh/Qnl (normalized), k->Kh + ksum, v->Vf
    proj_kernel<<<dim3(4, 32, 3), 256, SMP>>>(XH, XL, WH, bq, bk, bv,
                                              Qnh, Qnl, Kh, Vf, ks);

    // 2: Kn (column-normalize) -> fp16 (x2048)
    knorm_kernel<<<2048, 256>>>(Kh, ks, Knh);

    // 3: fused att (1-term, streamed) + s_part (overlapped, z=0,1)
    att_spart_kernel<<<dim3(16, 16, 18), 256, ATT_SMEM>>>(Qnh, Knh, Vf, att, Spart);

    // 4: S reduce, then OH = Qn @ S -> fp16 hi/lo
    s_reduce_kernel<<<64, 1024>>>(Spart, S);
    oh_kernel<<<dim3(16, 16), 256>>>(Qnh, Qnl, S, OHh, OHl);

    // 5: final projection, 2-term -> d_out
    mm_kernel<2><<<dim3(4, 32, 1), 256, SMP>>>(
        OHh, OHl, DM, WH + 3LL * DM * DM, nullptr, DM, out, DM, DM, bo, 0, 1, 1.f);
}

// round 9
// speedup vs baseline: 2.0853x; 1.0105x over previous
#include <cuda_runtime.h>
#include <cuda_fp16.h>
#include <cstdint>

#define NTOK   4096          // B*N = 2*2048
#define DM     512
#define NSEQ   2048
#define NHEADS 8
#define DK     64

#define QSCALE 64.0f
#define KSCALE 2048.0f
#define ATT_CSCALE (1.0f / (64.0f * 2048.0f))
#define OH_CSCALE  (1.0f / (64.0f * 2048.0f))

// ---------------- scratch (__device__ globals; no allocs allowed) ----------
__device__ float g_Vf[NTOK * DM];                             // V fp32
__device__ __half g_XH[3 * NTOK * DM], g_XL[3 * NTOK * DM];   // q,k,v hi/lo
__device__ __half g_WH[4 * DM * DM],  g_WL[4 * DM * DM];      // Wq,Wk,Wv,Wo
__device__ __half g_Qnh[NTOK * DM], g_Qnl[NTOK * DM];         // Qn * 64 (exact pair)
__device__ __half g_Kh[NTOK * DM];                            // elu(K)+1, fp16
__device__ float g_ksum[1024];                                // per (b, d) col sums
__device__ float g_Spart[32 * 16 * DK * DK];                  // scaled x2048
__device__ float g_S[16 * DK * DK];                           // scaled x2048
__device__ __half g_OHh[NTOK * DM], g_OHl[NTOK * DM];

// ---------------- helpers ---------------------------------------------------
__device__ __forceinline__ void cvt_split(float x, __half& hi, __half& lo) {
    hi = __float2half_rn(x);
    lo = __float2half_rn(x - __half2float(hi));
}
__device__ __forceinline__ uint32_t pack2(__half a, __half b) {
    __half2 t(a, b);
    return *reinterpret_cast<uint32_t*>(&t);
}
__device__ __forceinline__ uint32_t smem_u32(const void* p) {
    uint32_t a;
    asm("{ .reg .u64 t; cvta.to.shared.u64 t, %1; cvt.u32.u64 %0, t; }" : "=r"(a) : "l"(p));
    return a;
}
__device__ __forceinline__ void mma16816(float* c, const uint32_t* a, const uint32_t* b) {
    asm volatile(
        "mma.sync.aligned.m16n8k16.row.col.f32.f16.f16.f32 "
        "{%0,%1,%2,%3},{%4,%5,%6,%7},{%8,%9},{%0,%1,%2,%3};"
        : "+f"(c[0]), "+f"(c[1]), "+f"(c[2]), "+f"(c[3])
        : "r"(a[0]), "r"(a[1]), "r"(a[2]), "r"(a[3]), "r"(b[0]), "r"(b[1]));
}
__device__ __forceinline__ void ldsm4(uint32_t* r, uint32_t a) {
    asm volatile("ldmatrix.sync.aligned.m8n8.x4.shared.b16 {%0,%1,%2,%3},[%4];"
                 : "=r"(r[0]), "=r"(r[1]), "=r"(r[2]), "=r"(r[3]) : "r"(a));
}
__device__ __forceinline__ float elup1(float x) {
    return (x > 0.f) ? x + 1.f : expf(x);
}

// ---------------- one-shot fp32 -> fp16 hi/lo conversion (inputs + weights) -
// float4 linear space: [0, 3*NI4) inputs -> XH/XL ; [3*NI4, 3*NI4+4*NW4) -> WH/WL
#define NI4 (NTOK * DM / 4)
#define NW4 (DM * DM / 4)

__global__ void cvt_all_kernel(const float* __restrict__ q, const float* __restrict__ k,
                               const float* __restrict__ v,
                               const float* __restrict__ Wq, const float* __restrict__ Wk,
                               const float* __restrict__ Wv, const float* __restrict__ Wo,
                               __half* __restrict__ XH, __half* __restrict__ XL,
                               __half* __restrict__ WH, __half* __restrict__ WL,
                               float* __restrict__ ksum)
{
    if (blockIdx.x < 4) ksum[blockIdx.x * 256 + threadIdx.x] = 0.f;
    long long i4 = (long long)blockIdx.x * 256 + threadIdx.x;
    const float* src;
    __half *H, *L;
    long long off;
    if (i4 < 3LL * NI4) {
        int w = (int)(i4 / NI4);
        src = (w == 0) ? q : (w == 1) ? k : v;
        off = i4;
        H = XH; L = XL;
        i4 -= (long long)w * NI4;
    } else {
        long long j = i4 - 3LL * NI4;
        int w = (int)(j / NW4);
        src = (w == 0) ? Wq : (w == 1) ? Wk : (w == 2) ? Wv : Wo;
        off = j;
        H = WH; L = WL;
        i4 = j - (long long)w * NW4;
    }
    float4 vv = reinterpret_cast<const float4*>(src)[i4];
    __half a, b, c, d, e, f, g, hh;
    cvt_split(vv.x, a, e); cvt_split(vv.y, b, f);
    cvt_split(vv.z, c, g); cvt_split(vv.w, d, hh);
    uint2 ph; ph.x = pack2(a, b); ph.y = pack2(c, d);
    uint2 pl; pl.x = pack2(e, f); pl.y = pack2(g, hh);
    reinterpret_cast<uint2*>(H)[off] = ph;
    reinterpret_cast<uint2*>(L)[off] = pl;
}

// ---------------- shared GEMM plumbing --------------------------------------
#define GST   40                  // padded row: 32 elems + 8 (80B; LDSM conflict-free)
#define TILEB (128 * GST * 2)     // 10240 B per tile

// ---------------- fused projection kernel -----------------------------------
__global__ __launch_bounds__(256, 2)
void proj_kernel(const __half* __restrict__ XH, const __half* __restrict__ XL,
                 const __half* __restrict__ WH,
                 const float* __restrict__ bq, const float* __restrict__ bk,
                 const float* __restrict__ bv,
                 __half* __restrict__ Qnh, __half* __restrict__ Qnl,
                 __half* __restrict__ Kh, float* __restrict__ Vf,
                 float* __restrict__ ksum)
{
    extern __shared__ __half smem[];
    constexpr int STAGEB = 3 * TILEB;
    int zb = blockIdx.z;
    const __half* Ahi = XH + (long long)zb * NTOK * DM;
    const __half* Alo = XL + (long long)zb * NTOK * DM;
    const __half* Bhi = WH + (long long)zb * DM * DM;
    const float* bias = (zb == 0) ? bq : (zb == 1) ? bk : bv;

    int m0 = blockIdx.y * 128, n0 = blockIdx.x * 128;
    int tid = threadIdx.x, lane = tid & 31, warp = tid >> 5;
    int wm = (warp >> 1) * 32;
    int wn = (warp & 1) * 64;
    int grp = lane >> 2, tig = lane & 3;
    uint32_t sb = smem_u32(smem);

    int aoff = (wm + (lane & 15)) * GST + ((lane >> 4) << 3);
    int boff = (wn + ((lane >> 4) << 3) + (lane & 7)) * GST + (((lane >> 3) & 1) << 3);

    float acc[2][8][4];
    #pragma unroll
    for (int i = 0; i < 2; i++)
        #pragma unroll
        for (int j = 0; j < 8; j++)
            #pragma unroll
            for (int l = 0; l < 4; l++) acc[i][j][l] = 0.f;

    auto issue = [&](int s, int kt) {
        #pragma unroll
        for (int j = 0; j < 6; j++) {
            int id = tid + j * 256;
            int tile = id >> 9;
            int w = id & 511;
            int r = w >> 2, ce = (w & 3) * 8;
            const __half* src;
            if (tile == 0)      src = Ahi + (long long)(m0 + r) * DM + kt + ce;
            else if (tile == 1) src = Alo + (long long)(m0 + r) * DM + kt + ce;
            else                src = Bhi + (long long)(n0 + r) * DM + kt + ce;
            uint32_t d = sb + (uint32_t)(s * STAGEB + tile * TILEB) + (uint32_t)(r * GST + ce) * 2u;
            asm volatile("cp.async.cg.shared.global [%0],[%1],16;\n" :: "r"(d), "l"(src));
        }
        asm volatile("cp.async.commit_group;\n" ::);
    };

    issue(0, 0);
    for (int i = 0; i < 16; i++) {
        int cur = i & 1;
        if (i + 1 < 16) {
            issue(cur ^ 1, (i + 1) << 5);
            asm volatile("cp.async.wait_group 1;\n" ::);
        } else {
            asm volatile("cp.async.wait_group 0;\n" ::);
        }
        __syncthreads();
        uint32_t sA  = sb + cur * STAGEB;
        uint32_t sAl = sA + TILEB;
        uint32_t sB  = sA + 2 * TILEB;

        #pragma unroll
        for (int kk = 0; kk < 32; kk += 16) {
            uint32_t ah[2][4], al[2][4], bf[4][4];
            #pragma unroll
            for (int mi = 0; mi < 2; mi++)
                ldsm4(ah[mi], sA + (uint32_t)(aoff + mi * 16 * GST + kk) * 2u);
            #pragma unroll
            for (int n2 = 0; n2 < 4; n2++)
                ldsm4(bf[n2], sB + (uint32_t)(boff + n2 * 16 * GST + kk) * 2u);
            #pragma unroll
            for (int mi = 0; mi < 2; mi++)
                #pragma unroll
                for (int n2 = 0; n2 < 4; n2++) {
                    mma16816(acc[mi][2 * n2],     ah[mi], bf[n2]);
                    mma16816(acc[mi][2 * n2 + 1], ah[mi], bf[n2] + 2);
                }
            #pragma unroll
            for (int mi = 0; mi < 2; mi++)
                ldsm4(al[mi], sAl + (uint32_t)(aoff + mi * 16 * GST + kk) * 2u);
            #pragma unroll
            for (int mi = 0; mi < 2; mi++)
                #pragma unroll
                for (int n2 = 0; n2 < 4; n2++) {
                    mma16816(acc[mi][2 * n2],     al[mi], bf[n2]);
                    mma16816(acc[mi][2 * n2 + 1], al[mi], bf[n2] + 2);
                }
        }
        __syncthreads();
    }

    // ---- epilogue: bias (+ elu+1 for q,k) ----
    #pragma unroll
    for (int mi = 0; mi < 2; mi++)
        #pragma unroll
        for (int ni = 0; ni < 8; ni++) {
            int col = n0 + wn + ni * 8 + tig * 2;
            float bb0 = __ldg(&bias[col]), bb1 = __ldg(&bias[col + 1]);
            acc[mi][ni][0] += bb0; acc[mi][ni][1] += bb1;
            acc[mi][ni][2] += bb0; acc[mi][ni][3] += bb1;
            if (zb < 2) {
                acc[mi][ni][0] = elup1(acc[mi][ni][0]);
                acc[mi][ni][1] = elup1(acc[mi][ni][1]);
                acc[mi][ni][2] = elup1(acc[mi][ni][2]);
                acc[mi][ni][3] = elup1(acc[mi][ni][3]);
            }
        }

    if (zb == 0) {
        // Q: per-head row-normalize (warp's 64 cols = one full head)
        #pragma unroll
        for (int mi = 0; mi < 2; mi++) {
            float s0 = 0.f, s1 = 0.f;
            #pragma unroll
            for (int ni = 0; ni < 8; ni++) {
                s0 += acc[mi][ni][0] + acc[mi][ni][1];
                s1 += acc[mi][ni][2] + acc[mi][ni][3];
            }
            s0 += __shfl_xor_sync(0xffffffffu, s0, 1);
            s0 += __shfl_xor_sync(0xffffffffu, s0, 2);
            s1 += __shfl_xor_sync(0xffffffffu, s1, 1);
            s1 += __shfl_xor_sync(0xffffffffu, s1, 2);
            float inv0 = QSCALE / (s0 + 1e-8f);
            float inv1 = QSCALE / (s1 + 1e-8f);
            int r0 = m0 + wm + mi * 16 + grp;
            #pragma unroll
            for (int ni = 0; ni < 8; ni++) {
                int col = n0 + wn + ni * 8 + tig * 2;
                __half h0, l0, h1, l1;
                cvt_split(acc[mi][ni][0] * inv0, h0, l0);
                cvt_split(acc[mi][ni][1] * inv0, h1, l1);
                *reinterpret_cast<uint32_t*>(&Qnh[(long long)r0 * DM + col]) = pack2(h0, h1);
                *reinterpret_cast<uint32_t*>(&Qnl[(long long)r0 * DM + col]) = pack2(l0, l1);
                cvt_split(acc[mi][ni][2] * inv1, h0, l0);
                cvt_split(acc[mi][ni][3] * inv1, h1, l1);
                *reinterpret_cast<uint32_t*>(&Qnh[(long long)(r0 + 8) * DM + col]) = pack2(h0, h1);
                *reinterpret_cast<uint32_t*>(&Qnl[(long long)(r0 + 8) * DM + col]) = pack2(l0, l1);
            }
        }
    } else if (zb == 1) {
        // K: store fp16 + column-sum atomics
        int bb = m0 >> 11;
        #pragma unroll
        for (int ni = 0; ni < 8; ni++) {
            int col = n0 + wn + ni * 8 + tig * 2;
            float c0 = 0.f, c1 = 0.f;
            #pragma unroll
            for (int mi = 0; mi < 2; mi++) {
                int r0 = m0 + wm + mi * 16 + grp;
                c0 += acc[mi][ni][0] + acc[mi][ni][2];
                c1 += acc[mi][ni][1] + acc[mi][ni][3];
                *reinterpret_cast<uint32_t*>(&Kh[(long long)r0 * DM + col]) =
                    pack2(__float2half_rn(acc[mi][ni][0]), __float2half_rn(acc[mi][ni][1]));
                *reinterpret_cast<uint32_t*>(&Kh[(long long)(r0 + 8) * DM + col]) =
                    pack2(__float2half_rn(acc[mi][ni][2]), __float2half_rn(acc[mi][ni][3]));
            }
            c0 += __shfl_xor_sync(0xffffffffu, c0, 4);
            c0 += __shfl_xor_sync(0xffffffffu, c0, 8);
            c0 += __shfl_xor_sync(0xffffffffu, c0, 16);
            c1 += __shfl_xor_sync(0xffffffffu, c1, 4);
            c1 += __shfl_xor_sync(0xffffffffu, c1, 8);
            c1 += __shfl_xor_sync(0xffffffffu, c1, 16);
            if (grp == 0) {
                atomicAdd(&ksum[bb * DM + col], c0);
                atomicAdd(&ksum[bb * DM + col + 1], c1);
            }
        }
    } else {
        // V: fp32
        #pragma unroll
        for (int mi = 0; mi < 2; mi++)
            #pragma unroll
            for (int ni = 0; ni < 8; ni++) {
                int row = m0 + wm + mi * 16 + grp;
                int col = n0 + wn + ni * 8 + tig * 2;
                *reinterpret_cast<float2*>(Vf + (long long)row * DM + col) =
                    make_float2(acc[mi][ni][0], acc[mi][ni][1]);
                *reinterpret_cast<float2*>(Vf + (long long)(row + 8) * DM + col) =
                    make_float2(acc[mi][ni][2], acc[mi][ni][3]);
            }
    }
}

// ---------------- generic fp16 hi/lo GEMM (final projection) ----------------
__global__ __launch_bounds__(256, 2)
void mm2_kernel(const __half* __restrict__ Ahi, const __half* __restrict__ Alo,
                const __half* __restrict__ Bhi,
                float* __restrict__ C,
                const float* __restrict__ bias)
{
    extern __shared__ __half smem[];
    constexpr int STAGEB = 3 * TILEB;

    int m0 = blockIdx.y * 128, n0 = blockIdx.x * 128;
    int tid = threadIdx.x, lane = tid & 31, warp = tid >> 5;
    int wm = (warp >> 1) * 32;
    int wn = (warp & 1) * 64;
    int grp = lane >> 2, tig = lane & 3;
    uint32_t sb = smem_u32(smem);

    int aoff = (wm + (lane & 15)) * GST + ((lane >> 4) << 3);
    int boff = (wn + ((lane >> 4) << 3) + (lane & 7)) * GST + (((lane >> 3) & 1) << 3);

    float acc[2][8][4];
    #pragma unroll
    for (int i = 0; i < 2; i++)
        #pragma unroll
        for (int j = 0; j < 8; j++)
            #pragma unroll
            for (int l = 0; l < 4; l++) acc[i][j][l] = 0.f;

    auto issue = [&](int s, int kt) {
        #pragma unroll
        for (int j = 0; j < 6; j++) {
            int id = tid + j * 256;
            int tile = id >> 9;
            int w = id & 511;
            int r = w >> 2, ce = (w & 3) * 8;
            const __half* src;
            if (tile == 0)      src = Ahi + (long long)(m0 + r) * DM + kt + ce;
            else if (tile == 1) src = Alo + (long long)(m0 + r) * DM + kt + ce;
            else                src = Bhi + (long long)(n0 + r) * DM + kt + ce;
            uint32_t d = sb + (uint32_t)(s * STAGEB + tile * TILEB) + (uint32_t)(r * GST + ce) * 2u;
            asm volatile("cp.async.cg.shared.global [%0],[%1],16;\n" :: "r"(d), "l"(src));
        }
        asm volatile("cp.async.commit_group;\n" ::);
    };

    issue(0, 0);
    for (int i = 0; i < 16; i++) {
        int cur = i & 1;
        if (i + 1 < 16) {
            issue(cur ^ 1, (i + 1) << 5);
            asm volatile("cp.async.wait_group 1;\n" ::);
        } else {
            asm volatile("cp.async.wait_group 0;\n" ::);
        }
        __syncthreads();
        uint32_t sA  = sb + cur * STAGEB;
        uint32_t sAl = sA + TILEB;
        uint32_t sB  = sA + 2 * TILEB;

        #pragma unroll
        for (int kk = 0; kk < 32; kk += 16) {
            uint32_t ah[2][4], al[2][4], bf[4][4];
            #pragma unroll
            for (int mi = 0; mi < 2; mi++)
                ldsm4(ah[mi], sA + (uint32_t)(aoff + mi * 16 * GST + kk) * 2u);
            #pragma unroll
            for (int n2 = 0; n2 < 4; n2++)
                ldsm4(bf[n2], sB + (uint32_t)(boff + n2 * 16 * GST + kk) * 2u);
            #pragma unroll
            for (int mi = 0; mi < 2; mi++)
                #pragma unroll
                for (int n2 = 0; n2 < 4; n2++) {
                    mma16816(acc[mi][2 * n2],     ah[mi], bf[n2]);
                    mma16816(acc[mi][2 * n2 + 1], ah[mi], bf[n2] + 2);
                }
            #pragma unroll
            for (int mi = 0; mi < 2; mi++)
                ldsm4(al[mi], sAl + (uint32_t)(aoff + mi * 16 * GST + kk) * 2u);
            #pragma unroll
            for (int mi = 0; mi < 2; mi++)
                #pragma unroll
                for (int n2 = 0; n2 < 4; n2++) {
                    mma16816(acc[mi][2 * n2],     al[mi], bf[n2]);
                    mma16816(acc[mi][2 * n2 + 1], al[mi], bf[n2] + 2);
                }
        }
        __syncthreads();
    }

    #pragma unroll
    for (int mi = 0; mi < 2; mi++) {
        #pragma unroll
        for (int ni = 0; ni < 8; ni++) {
            int row = m0 + wm + mi * 16 + grp;
            int col = n0 + wn + ni * 8 + tig * 2;
            float bb0 = __ldg(&bias[col]), bb1 = __ldg(&bias[col + 1]);
            float2 p0 = make_float2(acc[mi][ni][0] + bb0, acc[mi][ni][1] + bb1);
            float2 p1 = make_float2(acc[mi][ni][2] + bb0, acc[mi][ni][3] + bb1);
            __stcs(reinterpret_cast<float2*>(C + (long long)row * DM + col), p0);
            __stcs(reinterpret_cast<float2*>(C + (long long)(row + 8) * DM + col), p1);
        }
    }
}

// ---------------- att: 1-term fp16 GEMM with in-smem K normalization --------
#define ATT_SMEM (2 * 2 * TILEB + 256)   // 2 stages x {A,B} + scale table

__global__ __launch_bounds__(256, 2)
void att_kernel(const __half* __restrict__ Qnh, const __half* __restrict__ Kh,
                const float* __restrict__ ksum, float* __restrict__ att)
{
    extern __shared__ char dsm[];
    int tid = threadIdx.x;
    int bh = blockIdx.z;
    int b = bh >> 3, h = bh & 7;
    const __half* A = Qnh + (long long)b * NSEQ * DM + h * DK;
    const __half* B = Kh + (long long)b * NSEQ * DM + h * DK;
    float* C = att + (long long)bh * NSEQ * NSEQ;
    float* sc = reinterpret_cast<float*>(dsm + 4 * TILEB);

    int m0 = blockIdx.y * 128, n0 = blockIdx.x * 128;
    int lane = tid & 31, warp = tid >> 5;
    int wm = (warp >> 1) * 32;
    int wn = (warp & 1) * 64;
    int grp = lane >> 2, tig = lane & 3;
    uint32_t sb = smem_u32(dsm);
    constexpr int STAGEB = 2 * TILEB;

    int aoff = (wm + (lane & 15)) * GST + ((lane >> 4) << 3);
    int boff = (wn + ((lane >> 4) << 3) + (lane & 7)) * GST + (((lane >> 3) & 1) << 3);

    float acc[2][8][4];
    #pragma unroll
    for (int i = 0; i < 2; i++)
        #pragma unroll
        for (int j = 0; j < 8; j++)
            #pragma unroll
            for (int l = 0; l < 4; l++) acc[i][j][4 - 4 + l] = 0.f;

    auto issue = [&](int s, int kt) {
        #pragma unroll
        for (int j = 0; j < 4; j++) {
            int id = tid + j * 256;
            int tile = id >> 9;
            int w = id & 511;
            int r = w >> 2, ce = (w & 3) * 8;
            const __half* src = (tile == 0)
                ? A + (long long)(m0 + r) * DM + kt + ce
                : B + (long long)(n0 + r) * DM + kt + ce;
            uint32_t d = sb + (uint32_t)(s * STAGEB + tile * TILEB) + (uint32_t)(r * GST + ce) * 2u;
            asm volatile("cp.async.cg.shared.global [%0],[%1],16;\n" :: "r"(d), "l"(src));
        }
        asm volatile("cp.async.commit_group;\n" ::);
    };

    issue(0, 0);
    if (tid < 64) sc[tid] = KSCALE / (__ldg(&ksum[b * DM + h * DK + tid]) + 1e-8f);
    #pragma unroll
    for (int i = 0; i < 2; i++) {
        if (i == 0) {
            issue(1, 32);
            asm volatile("cp.async.wait_group 1;\n" ::);
        } else {
            asm volatile("cp.async.wait_group 0;\n" ::);
        }
        __syncthreads();
        // normalize the K tile (B operand) in smem: x KSCALE/ksum[d]
        {
            char* bbase = dsm + i * STAGEB + TILEB;
            #pragma unroll
            for (int j = 0; j < 8; j++) {
                int id = tid + j * 256;
                int r = id >> 4, c = (id & 15) * 2;
                __half2* p = reinterpret_cast<__half2*>(bbase + (uint32_t)(r * GST + c) * 2u);
                float2 f = __half22float2(*p);
                f.x *= sc[i * 32 + c];
                f.y *= sc[i * 32 + c + 1];
                *p = __floats2half2_rn(f.x, f.y);
            }
        }
        __syncthreads();
        uint32_t sA = sb + i * STAGEB;
        uint32_t sB = sA + TILEB;
        #pragma unroll
        for (int kk = 0; kk < 32; kk += 16) {
            uint32_t ah[2][4], bf[4][4];
            #pragma unroll
            for (int mi = 0; mi < 2; mi++)
                ldsm4(ah[mi], sA + (uint32_t)(aoff + mi * 16 * GST + kk) * 2u);
            #pragma unroll
            for (int n2 = 0; n2 < 4; n2++)
                ldsm4(bf[n2], sB + (uint32_t)(boff + n2 * 16 * GST + kk) * 2u);
            #pragma unroll
            for (int mi = 0; mi < 2; mi++)
                #pragma unroll
                for (int n2 = 0; n2 < 4; n2++) {
                    mma16816(acc[mi][2 * n2],     ah[mi], bf[n2]);
                    mma16816(acc[mi][2 * n2 + 1], ah[mi], bf[n2] + 2);
                }
        }
        __syncthreads();
    }

    #pragma unroll
    for (int mi = 0; mi < 2; mi++) {
        #pragma unroll
        for (int ni = 0; ni < 8; ni++) {
            int row = m0 + wm + mi * 16 + grp;
            int col = n0 + wn + ni * 8 + tig * 2;
            float2 p0 = make_float2(acc[mi][ni][0] * ATT_CSCALE, acc[mi][ni][1] * ATT_CSCALE);
            float2 p1 = make_float2(acc[mi][ni][2] * ATT_CSCALE, acc[mi][ni][3] * ATT_CSCALE);
            __stcs(reinterpret_cast<float2*>(C + (long long)row * NSEQ + col), p0);
            __stcs(reinterpret_cast<float2*>(C + (long long)(row + 8) * NSEQ + col), p1);
        }
    }
}

// ---------------- spart: Kn^T V chunk partials (fp32 SIMT) ------------------
__global__ void spart_kernel(const __half* __restrict__ Kh, const float* __restrict__ ksum,
                             const float* __restrict__ Vf, float* __restrict__ Spart)
{
    __shared__ float Kt[64 * 64];
    __shared__ float Vt[64 * 64];
    __shared__ float sc[64];
    int chunk = blockIdx.x, bh = blockIdx.y;
    int b = bh >> 3, h = bh & 7;
    int tid = threadIdx.x;
    int d = tid & 63, qq = tid >> 6;
    if (tid < 64) sc[tid] = KSCALE / (__ldg(&ksum[b * DM + h * DK + tid]) + 1e-8f);
    __syncthreads();
    float acc[16];
    #pragma unroll
    for (int j = 0; j < 16; j++) acc[j] = 0.f;
    long long base = ((long long)b * NSEQ + chunk * 64) * DM + h * DK;
    #pragma unroll
    for (int j = 0; j < 16; j++) {
        int idd = tid + j * 256;
        int nl = idd >> 6, dd = idd & 63;
        Kt[nl * 64 + dd] = __half2float(Kh[base + (long long)nl * DM + dd]) * sc[dd];
        Vt[nl * 64 + dd] = Vf[base + (long long)nl * DM + dd];
    }
    __syncthreads();
    for (int nn = 0; nn < 64; nn++) {
        float kv = Kt[nn * 64 + d];
        const float4* vr = reinterpret_cast<const float4*>(&Vt[nn * 64 + qq * 16]);
        #pragma unroll
        for (int j4 = 0; j4 < 4; j4++) {
            float4 v = vr[j4];
            acc[j4 * 4 + 0] += kv * v.x;
            acc[j4 * 4 + 1] += kv * v.y;
            acc[j4 * 4 + 2] += kv * v.z;
            acc[j4 * 4 + 3] += kv * v.w;
        }
    }
    float* o = Spart + ((long long)chunk * 16 + bh) * (DK * DK) + d * DK + qq * 16;
    #pragma unroll
    for (int j4 = 0; j4 < 4; j4++)
        reinterpret_cast<float4*>(o)[j4] =
            make_float4(acc[j4 * 4], acc[j4 * 4 + 1], acc[j4 * 4 + 2], acc[j4 * 4 + 3]);
}

__global__ void s_reduce_kernel(const float* __restrict__ Spart, float* __restrict__ S) {
    int i = blockIdx.x * 1024 + threadIdx.x;
    float s = 0.f;
    #pragma unroll
    for (int c = 0; c < 32; c++) s += Spart[(long long)c * 65536 + i];
    S[i] = s;
}

// ---------------- OH = Qn @ S per (b,h) -------------------------------------
__global__ void oh_kernel(const __half* __restrict__ Qnh, const __half* __restrict__ Qnl,
                          const float* __restrict__ S,
                          __half* __restrict__ OHh, __half* __restrict__ OHl) {
    int mc = blockIdx.x;
    int bh = blockIdx.y;
    int b = bh >> 3, h = bh & 7;
    int t = threadIdx.x;
    int e4 = t & 15, r = t >> 4;
    __shared__ float Ss[64][64];
    __shared__ float Qs[16][64];
    #pragma unroll
    for (int j = 0; j < 16; j++) {
        int id = t + j * 256;
        Ss[id >> 6][id & 63] = S[(long long)bh * (DK * DK) + id];
    }
    for (int it = 0; it < 8; it++) {
        int mrow = mc * 128 + it * 16;
        __syncthreads();
        #pragma unroll
        for (int j = 0; j < 4; j++) {
            int id = t + j * 256;
            int rr = id >> 6, dd = id & 63;
            long long qidx = ((long long)b * NSEQ + mrow + rr) * DM + h * DK + dd;
            Qs[rr][dd] = __half2float(Qnh[qidx]) + __half2float(Qnl[qidx]);
        }
        __syncthreads();
        float4 a = make_float4(0.f, 0.f, 0.f, 0.f);
        #pragma unroll
        for (int dd = 0; dd < 64; dd++) {
            float qd = Qs[r][dd];
            float4 s4 = *reinterpret_cast<const float4*>(&Ss[dd][e4 * 4]);
            a.x += qd * s4.x; a.y += qd * s4.y; a.z += qd * s4.z; a.w += qd * s4.w;
        }
        __half h0, h1, h2, h3, l0, l1, l2, l3;
        cvt_split(a.x * OH_CSCALE, h0, l0); cvt_split(a.y * OH_CSCALE, h1, l1);
        cvt_split(a.z * OH_CSCALE, h2, l2); cvt_split(a.w * OH_CSCALE, h3, l3);
        long long oidx = ((long long)b * NSEQ + mrow + r) * DM + h * DK + e4 * 4;
        uint2 ph; ph.x = pack2(h0, h1); ph.y = pack2(h2, h3);
        uint2 pl; pl.x = pack2(l0, l1); pl.y = pack2(l2, l3);
        *reinterpret_cast<uint2*>(OHh + oidx) = ph;
        *reinterpret_cast<uint2*>(OHl + oidx) = pl;
    }
}

// ---------------- launch ----------------------------------------------------
extern "C" void kernel_launch(void* const* d_in, const int* in_sizes, int n_in,
                              void* d_out, int out_size) {
    const float* q  = (const float*)d_in[0];
    const float* k  = (const float*)d_in[1];
    const float* v  = (const float*)d_in[2];
    const float* Wq = (const float*)d_in[3];
    const float* bq = (const float*)d_in[4];
    const float* Wk = (const float*)d_in[5];
    const float* bk = (const float*)d_in[6];
    const float* Wv = (const float*)d_in[7];
    const float* bv = (const float*)d_in[8];
    const float* Wo = (const float*)d_in[9];
    const float* bo = (const float*)d_in[10];

    float* out = (float*)d_out;                       // [2,2048,512]
    float* att = out + (long long)NTOK * DM;          // [2,8,2048,2048]

    float *Vf, *ks, *Spart, *S;
    __half *XH, *XL, *WH, *WL, *Qnh, *Qnl, *Kh, *OHh, *OHl;
    cudaGetSymbolAddress((void**)&Vf, g_Vf);
    cudaGetSymbolAddress((void**)&ks, g_ksum);
    cudaGetSymbolAddress((void**)&Spart, g_Spart);
    cudaGetSymbolAddress((void**)&S, g_S);
    cudaGetSymbolAddress((void**)&XH, g_XH);  cudaGetSymbolAddress((void**)&XL, g_XL);
    cudaGetSymbolAddress((void**)&WH, g_WH);  cudaGetSymbolAddress((void**)&WL, g_WL);
    cudaGetSymbolAddress((void**)&Qnh, g_Qnh); cudaGetSymbolAddress((void**)&Qnl, g_Qnl);
    cudaGetSymbolAddress((void**)&Kh, g_Kh);
    cudaGetSymbolAddress((void**)&OHh, g_OHh); cudaGetSymbolAddress((void**)&OHl, g_OHl);

    constexpr int SMP = 2 * 3 * TILEB;   // 61440
    cudaFuncSetAttribute(proj_kernel, cudaFuncAttributeMaxDynamicSharedMemorySize, SMP);
    cudaFuncSetAttribute(mm2_kernel, cudaFuncAttributeMaxDynamicSharedMemorySize, SMP);
    cudaFuncSetAttribute(att_kernel, cudaFuncAttributeMaxDynamicSharedMemorySize, ATT_SMEM);

    // lazily-created side stream + events (first call is the uncaptured
    // correctness run; subsequent captured calls replay identical work)
    static cudaStream_t s2 = nullptr;
    static cudaEvent_t evFork = nullptr, evJoin = nullptr;
    if (!s2) {
        cudaStreamCreateWithFlags(&s2, cudaStreamNonBlocking);
        cudaEventCreateWithFlags(&evFork, cudaEventDisableTiming);
        cudaEventCreateWithFlags(&evJoin, cudaEventDisableTiming);
    }

    // 0: one-shot conversions (+ zero ksum)
    cvt_all_kernel<<<(3 * NI4 + 4 * NW4) / 256, 256>>>(q, k, v, Wq, Wk, Wv, Wo,
                                                       XH, XL, WH, WL, ks);

    // 1: fused projections: q->Qnh/Qnl (normalized), k->Kh + ksum, v->Vf
    proj_kernel<<<dim3(4, 32, 3), 256, SMP>>>(XH, XL, WH, bq, bk, bv,
                                              Qnh, Qnl, Kh, Vf, ks);

    // fork: side chain (spart -> s_reduce -> oh -> final proj) on s2,
    // overlapped with the big att GEMM on the main stream.
    cudaEventRecord(evFork, 0);
    cudaStreamWaitEvent(s2, evFork, 0);

    spart_kernel<<<dim3(32, 16), 256, 0, s2>>>(Kh, ks, Vf, Spart);
    s_reduce_kernel<<<64, 1024, 0, s2>>>(Spart, S);
    oh_kernel<<<dim3(16, 16), 256, 0, s2>>>(Qnh, Qnl, S, OHh, OHl);
    mm2_kernel<<<dim3(4, 32, 1), 256, SMP, s2>>>(OHh, OHl, WH + 3LL * DM * DM, out, bo);
    cudaEventRecord(evJoin, s2);

    // main: attention_weights = Qn @ Kn^T (K normalized in-smem), streamed
    att_kernel<<<dim3(16, 16, 16), 256, ATT_SMEM>>>(Qnh, Kh, ks, att);

    cudaStreamWaitEvent(0, evJoin, 0);
}